// round 2
// baseline (speedup 1.0000x reference)
#include <cuda_runtime.h>
#include <cfloat>

#define NN 8192
#define DD 128
#define CC 64
#define FMARGIN 0.5f
#define NSPLIT 4
#define JSPAN (NN / NSPLIT)     // 2048
#define BI 128
#define BJ 128
#define NTILES (JSPAN / BJ)     // 16
#define SROW 132                // padded floats per smem tile row

typedef unsigned long long u64;

// packed dual-FMA: d.lo += a.lo*b.lo ; d.hi += a.hi*b.hi
__device__ __forceinline__ void ffma2(u64& d, u64 a, u64 b) {
    asm("fma.rn.f32x2 %0, %1, %2, %0;" : "+l"(d) : "l"(a), "l"(b));
}
__device__ __forceinline__ float hsum2(u64 v) {
    float lo = __uint_as_float((unsigned)(v & 0xffffffffull));
    float hi = __uint_as_float((unsigned)(v >> 32));
    return lo + hi;
}

// ---------------- device scratch (no allocations allowed) ----------------
__device__ float g_xn[NN];
__device__ int   g_ps[CC * NN];        // inclusive prefix count per class
__device__ int   g_hist[CC];
__device__ float g_pv[NN * NSPLIT];
__device__ int   g_pi[NN * NSPLIT];
__device__ float g_nv[NN * NSPLIT];
__device__ int   g_ni[NN * NSPLIT];
__device__ float g_part[64 * 9];

// ---------------- K0: row squared norms ----------------
__global__ void xn_kernel(const float* __restrict__ x) {
    int row = blockIdx.x * blockDim.x + threadIdx.x;   // 64 x 128 = 8192
    const float4* xr = reinterpret_cast<const float4*>(x) + (size_t)row * 32;
    float s = 0.0f;
    #pragma unroll
    for (int q = 0; q < 32; q++) {
        float4 v = xr[q];
        s = fmaf(v.x, v.x, s);
        s = fmaf(v.y, v.y, s);
        s = fmaf(v.z, v.z, s);
        s = fmaf(v.w, v.w, s);
    }
    g_xn[row] = s;
}

// ---------------- K1: per-class inclusive prefix counts ----------------
__global__ void prefix_kernel(const int* __restrict__ tg) {
    int c = blockIdx.x;                 // one block per class
    __shared__ int wsum[8];
    __shared__ int wpre[8];
    __shared__ int stot;
    int lane = threadIdx.x & 31, wid = threadIdx.x >> 5;
    int run = 0;
    for (int base = 0; base < NN; base += 256) {
        int f = (tg[base + threadIdx.x] == c) ? 1 : 0;
        int s = f;
        #pragma unroll
        for (int o = 1; o < 32; o <<= 1) {
            int v = __shfl_up_sync(0xffffffffu, s, o);
            if (lane >= o) s += v;
        }
        if (lane == 31) wsum[wid] = s;
        __syncthreads();
        if (threadIdx.x == 0) {
            int a = 0;
            for (int w = 0; w < 8; w++) { wpre[w] = a; a += wsum[w]; }
            stot = a;
        }
        __syncthreads();
        g_ps[c * NN + base + threadIdx.x] = run + wpre[wid] + s;
        run += stot;
        __syncthreads();
    }
    if (threadIdx.x == 0) g_hist[c] = run;
}

// ---------------- K2: masked argmax/argmin over pairwise distances ----------------
// score s = xn_j - 2*dot(x_i, x_j)  (row-monotone transform of d_ij)
__global__ void __launch_bounds__(256, 1)
dist_kernel(const float* __restrict__ x, const int* __restrict__ tg) {
    extern __shared__ float smem[];
    float* As  = smem;                       // BI*SROW
    float* Bs  = As + BI * SROW;             // BJ*SROW
    float* sxn = Bs + BJ * SROW;             // 128
    int*   st  = (int*)(sxn + BJ);           // 128
    float* rpv = (float*)(st + BJ);          // 128*16
    float* rnv = rpv + BI * 16;
    int*   rpi = (int*)(rnv + BI * 16);
    int*   rni = rpi + BI * 16;

    const int tid = threadIdx.x;
    const int ty = tid >> 4;                 // 0..15 (i group)
    const int tx = tid & 15;                 // 0..15 (j group)
    const int ib = blockIdx.x * BI;
    const int jb0 = blockIdx.y * JSPAN;

    // stationary A tile (rows), coalesced copy, padded rows
    for (int l = tid; l < BI * 32; l += 256) {
        int r = l >> 5, q = l & 31;
        float4 v = reinterpret_cast<const float4*>(x)[(size_t)(ib + r) * 32 + q];
        *reinterpret_cast<float4*>(&As[r * SROW + q * 4]) = v;
    }

    int ti[8];
    #pragma unroll
    for (int ii = 0; ii < 8; ii++) ti[ii] = tg[ib + ii * 16 + ty];

    float bpv[8], bnv[8];
    int bpi[8], bni[8];
    #pragma unroll
    for (int ii = 0; ii < 8; ii++) {
        bpv[ii] = -FLT_MAX; bnv[ii] = FLT_MAX; bpi[ii] = NN; bni[ii] = NN;
    }

    for (int t = 0; t < NTILES; t++) {
        const int jb = jb0 + t * BJ;
        __syncthreads();                     // previous consumers done with Bs/sxn/st
        for (int l = tid; l < BJ * 32; l += 256) {
            int r = l >> 5, q = l & 31;
            float4 v = reinterpret_cast<const float4*>(x)[(size_t)(jb + r) * 32 + q];
            *reinterpret_cast<float4*>(&Bs[r * SROW + q * 4]) = v;
        }
        if (tid < BJ) { sxn[tid] = g_xn[jb + tid]; st[tid] = tg[jb + tid]; }
        __syncthreads();

        // packed accumulators: lane0 = even-k partial, lane1 = odd-k partial
        u64 acc[8][8];
        #pragma unroll
        for (int ii = 0; ii < 8; ii++) {
            #pragma unroll
            for (int jj = 0; jj < 8; jj++) acc[ii][jj] = 0ull;
        }

        #pragma unroll 1
        for (int kq = 0; kq < 32; kq++) {
            u64 a0[8], a1[8];
            #pragma unroll
            for (int ii = 0; ii < 8; ii++) {
                const u64* ap = reinterpret_cast<const u64*>(
                    &As[(ii * 16 + ty) * SROW + kq * 4]);
                a0[ii] = ap[0];
                a1[ii] = ap[1];
            }
            #pragma unroll
            for (int jj = 0; jj < 8; jj++) {
                const u64* bp = reinterpret_cast<const u64*>(
                    &Bs[(jj * 16 + tx) * SROW + kq * 4]);
                u64 b0 = bp[0];
                u64 b1 = bp[1];
                #pragma unroll
                for (int ii = 0; ii < 8; ii++) {
                    ffma2(acc[ii][jj], a0[ii], b0);
                    ffma2(acc[ii][jj], a1[ii], b1);
                }
            }
        }

        // fold this tile into the running bests (j ascending within each thread)
        #pragma unroll
        for (int jj = 0; jj < 8; jj++) {
            int jl = jj * 16 + tx;
            float xnj = sxn[jl];
            int tj = st[jl];
            int j = jb + jl;
            #pragma unroll
            for (int ii = 0; ii < 8; ii++) {
                float dot = hsum2(acc[ii][jj]);
                float s = fmaf(-2.0f, dot, xnj);
                if (tj == ti[ii]) {
                    if (s > bpv[ii]) { bpv[ii] = s; bpi[ii] = j; }
                } else {
                    if (s < bnv[ii]) { bnv[ii] = s; bni[ii] = j; }
                }
            }
        }
    }

    // cross-thread merge per row (16 tx partials), tie -> smaller index
    __syncthreads();
    #pragma unroll
    for (int ii = 0; ii < 8; ii++) {
        int rl = ii * 16 + ty;
        rpv[rl * 16 + tx] = bpv[ii];
        rnv[rl * 16 + tx] = bnv[ii];
        rpi[rl * 16 + tx] = bpi[ii];
        rni[rl * 16 + tx] = bni[ii];
    }
    __syncthreads();
    if (tid < BI) {
        float pv = -FLT_MAX, nv = FLT_MAX;
        int pix = NN, nix = NN;
        #pragma unroll
        for (int k = 0; k < 16; k++) {
            float v = rpv[tid * 16 + k]; int id = rpi[tid * 16 + k];
            if (v > pv || (v == pv && id < pix)) { pv = v; pix = id; }
            v = rnv[tid * 16 + k]; id = rni[tid * 16 + k];
            if (v < nv || (v == nv && id < nix)) { nv = v; nix = id; }
        }
        int o = (ib + tid) * NSPLIT + blockIdx.y;
        g_pv[o] = pv; g_pi[o] = pix; g_nv[o] = nv; g_ni[o] = nix;
    }
}

// ---------------- K3: merge splits, gather triplets, per-block partial sums ----------------
__global__ void terms_kernel(const float* __restrict__ x, const int* __restrict__ tg) {
    __shared__ float red[128];
    int tid = threadIdx.x;
    int row = blockIdx.x * 128 + tid;

    float pv = -FLT_MAX, nv = FLT_MAX;
    int gp = NN, gn = NN;
    #pragma unroll
    for (int s2 = 0; s2 < NSPLIT; s2++) {
        int o = row * NSPLIT + s2;
        float v = g_pv[o]; int id = g_pi[o];
        if (v > pv || (v == pv && id < gp)) { pv = v; gp = id; }
        v = g_nv[o]; id = g_ni[o];
        if (v < nv || (v == nv && id < gn)) { nv = v; gn = id; }
    }
    int t = tg[row];
    int cs = g_hist[t];
    float vf = (cs > 1 && (NN - cs) >= 1) ? 1.0f : 0.0f;
    gp = min(max(gp, 0), NN - 1);
    gn = min(max(gn, 0), NN - 1);
    int ppos = g_ps[t * NN + gp] - 1;          // rank within same-class subset
    int pneg = gn - g_ps[t * NN + gn];          // rank within diff-class subset
    ppos = min(max(ppos, 0), NN - 1);
    pneg = min(max(pneg, 0), NN - 1);

    const float4* A = reinterpret_cast<const float4*>(x) + (size_t)row * 32;
    const float4* P = reinterpret_cast<const float4*>(x) + (size_t)ppos * 32;
    const float4* Q = reinterpret_cast<const float4*>(x) + (size_t)pneg * 32;
    float ap = 0, an = 0, npd = 0, l1a = 0, l1p = 0, l1n = 0;
    #pragma unroll
    for (int q = 0; q < 32; q++) {
        float4 a = A[q], p = P[q], n = Q[q];
        float d;
        d = a.x - p.x; ap = fmaf(d, d, ap);
        d = a.y - p.y; ap = fmaf(d, d, ap);
        d = a.z - p.z; ap = fmaf(d, d, ap);
        d = a.w - p.w; ap = fmaf(d, d, ap);
        d = a.x - n.x; an = fmaf(d, d, an);
        d = a.y - n.y; an = fmaf(d, d, an);
        d = a.z - n.z; an = fmaf(d, d, an);
        d = a.w - n.w; an = fmaf(d, d, an);
        d = p.x - n.x; npd = fmaf(d, d, npd);
        d = p.y - n.y; npd = fmaf(d, d, npd);
        d = p.z - n.z; npd = fmaf(d, d, npd);
        d = p.w - n.w; npd = fmaf(d, d, npd);
        l1a += fabsf(a.x) + fabsf(a.y) + fabsf(a.z) + fabsf(a.w);
        l1p += fabsf(p.x) + fabsf(p.y) + fabsf(p.z) + fabsf(p.w);
        l1n += fabsf(n.x) + fabsf(n.y) + fabsf(n.z) + fabsf(n.w);
    }
    float tl = fmaxf(ap - an + FMARGIN, 0.0f) * vf;

    float vals[9];
    vals[0] = tl;
    vals[1] = (tl > 0.0f) ? 1.0f : 0.0f;
    vals[2] = l1a * vf;
    vals[3] = l1p * vf;
    vals[4] = l1n * vf;
    vals[5] = ap * vf;
    vals[6] = an * vf;
    vals[7] = (ap - an - npd) * vf;
    vals[8] = vf;

    for (int k = 0; k < 9; k++) {
        red[tid] = vals[k];
        __syncthreads();
        for (int s = 64; s > 0; s >>= 1) {
            if (tid < s) red[tid] += red[tid + s];
            __syncthreads();
        }
        if (tid == 0) g_part[blockIdx.x * 9 + k] = red[0];
        __syncthreads();
    }
}

// ---------------- K4: finalize 6 scalars ----------------
__global__ void final_kernel(float* __restrict__ out, int out_size) {
    __shared__ float r[6];
    if (threadIdx.x == 0) {
        float s[9];
        for (int k = 0; k < 9; k++) s[k] = 0.0f;
        for (int b = 0; b < 64; b++)
            for (int k = 0; k < 9; k++) s[k] += g_part[b * 9 + k];
        float vcount = s[8];
        float inv = (vcount > 0.0f) ? (1.0f / vcount) : 0.0f;
        float trip = (s[1] > 0.0f) ? (s[0] / s[1]) : (s[0] * inv);
        float sparse = (s[2] + s[3] + s[4]) * inv * (1.0f / 3.0f);
        float pw = s[7] * inv;
        if (pw < 0.0f) pw = 0.0f;
        r[0] = trip; r[1] = sparse; r[2] = pw;
        r[3] = vcount; r[4] = s[5] * inv; r[5] = s[6] * inv;
    }
    __syncthreads();
    for (int i = threadIdx.x; i < out_size; i += blockDim.x)
        out[i] = (i < 6) ? r[i] : 0.0f;
}

// ---------------- launch ----------------
extern "C" void kernel_launch(void* const* d_in, const int* in_sizes, int n_in,
                              void* d_out, int out_size) {
    const float* x = (const float*)d_in[0];
    const int* tg = (const int*)d_in[1];

    const size_t smem_bytes =
        (size_t)(BI * SROW + BJ * SROW + BJ + BJ + 4 * BI * 16) * 4;  // 168,960 B
    cudaFuncSetAttribute(dist_kernel, cudaFuncAttributeMaxDynamicSharedMemorySize,
                         (int)smem_bytes);

    xn_kernel<<<64, 128>>>(x);
    prefix_kernel<<<CC, 256>>>(tg);
    dist_kernel<<<dim3(NN / BI, NSPLIT), 256, smem_bytes>>>(x, tg);
    terms_kernel<<<64, 128>>>(x, tg);
    final_kernel<<<1, 64>>>((float*)d_out, out_size);
}

// round 4
// speedup vs baseline: 1.0512x; 1.0512x over previous
#include <cuda_runtime.h>
#include <cfloat>
#include <cstdint>

#define NN 8192
#define DD 128
#define CC 64
#define FMARGIN 0.5f
#define NSPLIT 2
#define JSPAN (NN / NSPLIT)     // 4096
#define BI 128
#define BJ 64
#define NTILES (JSPAN / BJ)     // 64
#define SR 136                  // padded row stride in floats (128 + 8)

// ---------------- device scratch ----------------
__device__ float g_hi[NN * DD];
__device__ float g_lo[NN * DD];
__device__ float g_xn[NN];
__device__ int   g_ps[CC * NN];
__device__ int   g_hist[CC];
__device__ float g_pv[NN * NSPLIT];
__device__ int   g_pi[NN * NSPLIT];
__device__ float g_nv[NN * NSPLIT];
__device__ int   g_ni[NN * NSPLIT];
__device__ float g_part[64 * 9];

// ---------------- mma.sync m16n8k8 tf32 ----------------
__device__ __forceinline__ void mma_tf32(float* d, uint32_t a0, uint32_t a1,
                                         uint32_t a2, uint32_t a3,
                                         uint32_t b0, uint32_t b1) {
    asm volatile(
        "mma.sync.aligned.m16n8k8.row.col.f32.tf32.tf32.f32 "
        "{%0,%1,%2,%3}, {%4,%5,%6,%7}, {%8,%9}, {%0,%1,%2,%3};"
        : "+f"(d[0]), "+f"(d[1]), "+f"(d[2]), "+f"(d[3])
        : "r"(a0), "r"(a1), "r"(a2), "r"(a3), "r"(b0), "r"(b1));
}

// ---------------- K0: tf32 split + norms ----------------
__global__ void prep_kernel(const float* __restrict__ x) {
    int row = blockIdx.x * blockDim.x + threadIdx.x;
    const float4* xr = reinterpret_cast<const float4*>(x) + (size_t)row * 32;
    float4* hr = reinterpret_cast<float4*>(g_hi) + (size_t)row * 32;
    float4* lr = reinterpret_cast<float4*>(g_lo) + (size_t)row * 32;
    float s = 0.0f;
    #pragma unroll
    for (int q = 0; q < 32; q++) {
        float4 v = xr[q];
        float4 h, l;
        uint32_t u;
        asm("cvt.rna.tf32.f32 %0, %1;" : "=r"(u) : "f"(v.x)); h.x = __uint_as_float(u);
        asm("cvt.rna.tf32.f32 %0, %1;" : "=r"(u) : "f"(v.y)); h.y = __uint_as_float(u);
        asm("cvt.rna.tf32.f32 %0, %1;" : "=r"(u) : "f"(v.z)); h.z = __uint_as_float(u);
        asm("cvt.rna.tf32.f32 %0, %1;" : "=r"(u) : "f"(v.w)); h.w = __uint_as_float(u);
        float lx = v.x - h.x, ly = v.y - h.y, lz = v.z - h.z, lw = v.w - h.w;
        asm("cvt.rna.tf32.f32 %0, %1;" : "=r"(u) : "f"(lx)); l.x = __uint_as_float(u);
        asm("cvt.rna.tf32.f32 %0, %1;" : "=r"(u) : "f"(ly)); l.y = __uint_as_float(u);
        asm("cvt.rna.tf32.f32 %0, %1;" : "=r"(u) : "f"(lz)); l.z = __uint_as_float(u);
        asm("cvt.rna.tf32.f32 %0, %1;" : "=r"(u) : "f"(lw)); l.w = __uint_as_float(u);
        hr[q] = h; lr[q] = l;
        s = fmaf(v.x, v.x, s); s = fmaf(v.y, v.y, s);
        s = fmaf(v.z, v.z, s); s = fmaf(v.w, v.w, s);
    }
    g_xn[row] = s;
}

// ---------------- K1: per-class inclusive prefix counts ----------------
__global__ void prefix_kernel(const int* __restrict__ tg) {
    int c = blockIdx.x;
    __shared__ int wsum[8];
    __shared__ int wpre[8];
    __shared__ int stot;
    int lane = threadIdx.x & 31, wid = threadIdx.x >> 5;
    int run = 0;
    for (int base = 0; base < NN; base += 256) {
        int f = (tg[base + threadIdx.x] == c) ? 1 : 0;
        int s = f;
        #pragma unroll
        for (int o = 1; o < 32; o <<= 1) {
            int v = __shfl_up_sync(0xffffffffu, s, o);
            if (lane >= o) s += v;
        }
        if (lane == 31) wsum[wid] = s;
        __syncthreads();
        if (threadIdx.x == 0) {
            int a = 0;
            for (int w = 0; w < 8; w++) { wpre[w] = a; a += wsum[w]; }
            stot = a;
        }
        __syncthreads();
        g_ps[c * NN + base + threadIdx.x] = run + wpre[wid] + s;
        run += stot;
        __syncthreads();
    }
    if (threadIdx.x == 0) g_hist[c] = run;
}

// ---------------- helpers for the GEMM kernel ----------------
// Stage a 64-row x 128-col panel via registers (2 float4 per k-group of 8)
__device__ __forceinline__ void ldg_panel(const float* __restrict__ src, int jb,
                                          int tid, float4* s0, float4* s1) {
    int row = tid & 63;
    int kgb = tid >> 6;                   // 0..3
    #pragma unroll
    for (int u = 0; u < 4; u++) {
        const float* p = src + (size_t)(jb + row) * DD + (kgb + 4 * u) * 8;
        s0[u] = *reinterpret_cast<const float4*>(p);
        s1[u] = *reinterpret_cast<const float4*>(p + 4);
    }
}
// Store staged panel with k-pair interleave: word 2k=(f[k]), 2k+1=(f[k+4])
__device__ __forceinline__ void sts_panel(float* dst, int tid,
                                          const float4* s0, const float4* s1) {
    int row = tid & 63;
    int kgb = tid >> 6;
    #pragma unroll
    for (int u = 0; u < 4; u++) {
        float* b = dst + row * SR + (kgb + 4 * u) * 8;
        *reinterpret_cast<float2*>(b + 0) = make_float2(s0[u].x, s1[u].x);
        *reinterpret_cast<float2*>(b + 2) = make_float2(s0[u].y, s1[u].y);
        *reinterpret_cast<float2*>(b + 4) = make_float2(s0[u].z, s1[u].z);
        *reinterpret_cast<float2*>(b + 6) = make_float2(s0[u].w, s1[u].w);
    }
}

// One K=128 pass (optionally fused hi+lo A) over a 64-col B panel
template <bool WITH_LO>
__device__ __forceinline__ void gemm_phase(const float* __restrict__ Ahi,
                                           const float* __restrict__ Alo,
                                           const float* __restrict__ Bcur,
                                           float acc[2][4][4],
                                           int wm, int wn, int g, int tq) {
    #pragma unroll 4
    for (int kg = 0; kg < 16; kg++) {
        uint32_t bf0[4], bf1[4];
        #pragma unroll
        for (int n = 0; n < 4; n++) {
            float2 bb = *reinterpret_cast<const float2*>(
                Bcur + (wn * 32 + n * 8 + g) * SR + kg * 8 + 2 * tq);
            bf0[n] = __float_as_uint(bb.x);
            bf1[n] = __float_as_uint(bb.y);
        }
        #pragma unroll
        for (int m = 0; m < 2; m++) {
            int rb = (wm * 32 + m * 16 + g) * SR + kg * 8 + 2 * tq;
            float2 h02 = *reinterpret_cast<const float2*>(Ahi + rb);
            float2 h13 = *reinterpret_cast<const float2*>(Ahi + rb + 8 * SR);
            #pragma unroll
            for (int n = 0; n < 4; n++)
                mma_tf32(acc[m][n],
                         __float_as_uint(h02.x), __float_as_uint(h13.x),
                         __float_as_uint(h02.y), __float_as_uint(h13.y),
                         bf0[n], bf1[n]);
            if (WITH_LO) {
                float2 l02 = *reinterpret_cast<const float2*>(Alo + rb);
                float2 l13 = *reinterpret_cast<const float2*>(Alo + rb + 8 * SR);
                #pragma unroll
                for (int n = 0; n < 4; n++)
                    mma_tf32(acc[m][n],
                             __float_as_uint(l02.x), __float_as_uint(l13.x),
                             __float_as_uint(l02.y), __float_as_uint(l13.y),
                             bf0[n], bf1[n]);
            }
        }
    }
}

// smem word offsets
#define W_AHI 0
#define W_ALO 17408
#define W_B0  34816
#define W_B1  43520
#define W_SXN 52224
#define W_STG 52288
#define W_MPV 52352
#define W_MPI 52608
#define W_MNV 52864
#define W_MNI 53120
#define W_TOT 53376     // 213504 bytes

// ---------------- K2: 3xTF32 mma.sync masked argmax/argmin ----------------
__global__ void __launch_bounds__(256, 1)
dist_mma_kernel(const int* __restrict__ tg) {
    extern __shared__ float sm[];
    float* A_hi = sm + W_AHI;
    float* A_lo = sm + W_ALO;
    float* B0 = sm + W_B0;
    float* B1 = sm + W_B1;
    float* sxn = sm + W_SXN;
    int* stg = (int*)(sm + W_STG);
    float* mpv = sm + W_MPV;
    int* mpi = (int*)(sm + W_MPI);
    float* mnv = sm + W_MNV;
    int* mni = (int*)(sm + W_MNI);

    const int tid = threadIdx.x;
    const int lane = tid & 31;
    const int wid = tid >> 5;
    const int g = lane >> 2;             // 0..7
    const int tq = lane & 3;             // 0..3
    const int wm = wid >> 1;             // 0..3 (row group)
    const int wn = wid & 1;              // 0..1 (col group)
    const int ib = blockIdx.x * BI;
    const int jb0 = blockIdx.y * JSPAN;

    // --- preload A tiles (hi + lo), 128 rows, k-pair interleaved layout ---
    {
        int row = tid & 127;
        int kgb = tid >> 7;              // 0..1
        const float* ph = g_hi + (size_t)(ib + row) * DD;
        const float* pl = g_lo + (size_t)(ib + row) * DD;
        #pragma unroll
        for (int u = 0; u < 8; u++) {
            int kg = kgb + 2 * u;
            float4 q0 = *reinterpret_cast<const float4*>(ph + kg * 8);
            float4 q1 = *reinterpret_cast<const float4*>(ph + kg * 8 + 4);
            float* b = A_hi + row * SR + kg * 8;
            *reinterpret_cast<float2*>(b + 0) = make_float2(q0.x, q1.x);
            *reinterpret_cast<float2*>(b + 2) = make_float2(q0.y, q1.y);
            *reinterpret_cast<float2*>(b + 4) = make_float2(q0.z, q1.z);
            *reinterpret_cast<float2*>(b + 6) = make_float2(q0.w, q1.w);
            q0 = *reinterpret_cast<const float4*>(pl + kg * 8);
            q1 = *reinterpret_cast<const float4*>(pl + kg * 8 + 4);
            b = A_lo + row * SR + kg * 8;
            *reinterpret_cast<float2*>(b + 0) = make_float2(q0.x, q1.x);
            *reinterpret_cast<float2*>(b + 2) = make_float2(q0.y, q1.y);
            *reinterpret_cast<float2*>(b + 4) = make_float2(q0.z, q1.z);
            *reinterpret_cast<float2*>(b + 6) = make_float2(q0.w, q1.w);
        }
    }
    // --- preload B_hi(0) into B0 ---
    {
        float4 s0[4], s1[4];
        ldg_panel(g_hi, jb0, tid, s0, s1);
        sts_panel(B0, tid, s0, s1);
    }
    __syncthreads();

    // per-thread state: 4 owned rows (m-tile x half), fixed across j
    float bpv[4], bnv[4];
    int bpi[4], bni[4], ti_[4];
    #pragma unroll
    for (int r = 0; r < 4; r++) {
        bpv[r] = -FLT_MAX; bnv[r] = FLT_MAX; bpi[r] = NN; bni[r] = NN;
        ti_[r] = tg[ib + wm * 32 + (r >> 1) * 16 + (r & 1) * 8 + g];
    }
    float acc[2][4][4];
    #pragma unroll
    for (int m = 0; m < 2; m++)
        #pragma unroll
        for (int n = 0; n < 4; n++)
            #pragma unroll
            for (int c = 0; c < 4; c++) acc[m][n][c] = 0.0f;

    for (int t = 0; t < NTILES; t++) {
        const int jb = jb0 + t * BJ;

        // stage B_lo(t) + meta into registers (latency overlaps p0p1)
        float4 sl0[4], sl1[4];
        ldg_panel(g_lo, jb, tid, sl0, sl1);
        float myxn = 0.0f; int mytg = 0;
        if (tid < 64) { myxn = g_xn[jb + tid]; mytg = tg[jb + tid]; }

        // fused passes: hiA*hiB + loA*hiB on B0
        gemm_phase<true>(A_hi, A_lo, B0, acc, wm, wn, g, tq);

        // commit staged B_lo -> B1, meta -> smem
        sts_panel(B1, tid, sl0, sl1);
        if (tid < 64) { sxn[tid] = myxn; stg[tid] = mytg; }
        __syncthreads();

        // stage B_hi(t+1) (overlaps p2)
        float4 sh0[4], sh1[4];
        if (t + 1 < NTILES) ldg_panel(g_hi, jb + BJ, tid, sh0, sh1);

        // pass: hiA*loB on B1
        gemm_phase<false>(A_hi, A_lo, B1, acc, wm, wn, g, tq);

        // epilogue: scores + masked running argmax/argmin; reset acc
        #pragma unroll
        for (int n = 0; n < 4; n++) {
            int c0 = wn * 32 + n * 8 + 2 * tq;
            float xn0 = sxn[c0], xn1 = sxn[c0 + 1];
            int tg0 = stg[c0], tg1 = stg[c0 + 1];
            int j0 = jb + c0;
            #pragma unroll
            for (int m = 0; m < 2; m++) {
                #pragma unroll
                for (int h = 0; h < 2; h++) {
                    int ri = m * 2 + h;
                    float s0 = fmaf(-2.0f, acc[m][n][h * 2 + 0], xn0);
                    float s1 = fmaf(-2.0f, acc[m][n][h * 2 + 1], xn1);
                    if (tg0 == ti_[ri]) {
                        if (s0 > bpv[ri]) { bpv[ri] = s0; bpi[ri] = j0; }
                    } else {
                        if (s0 < bnv[ri]) { bnv[ri] = s0; bni[ri] = j0; }
                    }
                    if (tg1 == ti_[ri]) {
                        if (s1 > bpv[ri]) { bpv[ri] = s1; bpi[ri] = j0 + 1; }
                    } else {
                        if (s1 < bnv[ri]) { bnv[ri] = s1; bni[ri] = j0 + 1; }
                    }
                    acc[m][n][h * 2 + 0] = 0.0f;
                    acc[m][n][h * 2 + 1] = 0.0f;
                }
            }
        }

        if (t + 1 < NTILES) sts_panel(B0, tid, sh0, sh1);
        __syncthreads();
    }

    // quad merge (lanes sharing g, different tq → disjoint cols, same rows)
    #pragma unroll
    for (int r = 0; r < 4; r++) {
        #pragma unroll
        for (int off = 1; off <= 2; off <<= 1) {
            float ov = __shfl_xor_sync(0xffffffffu, bpv[r], off);
            int oi = __shfl_xor_sync(0xffffffffu, bpi[r], off);
            if (ov > bpv[r] || (ov == bpv[r] && oi < bpi[r])) { bpv[r] = ov; bpi[r] = oi; }
            ov = __shfl_xor_sync(0xffffffffu, bnv[r], off);
            oi = __shfl_xor_sync(0xffffffffu, bni[r], off);
            if (ov < bnv[r] || (ov == bnv[r] && oi < bni[r])) { bnv[r] = ov; bni[r] = oi; }
        }
    }
    if (tq == 0) {
        #pragma unroll
        for (int r = 0; r < 4; r++) {
            int row = wm * 32 + (r >> 1) * 16 + (r & 1) * 8 + g;
            mpv[wn * 128 + row] = bpv[r]; mpi[wn * 128 + row] = bpi[r];
            mnv[wn * 128 + row] = bnv[r]; mni[wn * 128 + row] = bni[r];
        }
    }
    __syncthreads();
    if (tid < 128) {
        float pv = mpv[tid]; int pi = mpi[tid];
        float v = mpv[128 + tid]; int id = mpi[128 + tid];
        if (v > pv || (v == pv && id < pi)) { pv = v; pi = id; }
        float nv = mnv[tid]; int ni = mni[tid];
        v = mnv[128 + tid]; id = mni[128 + tid];
        if (v < nv || (v == nv && id < ni)) { nv = v; ni = id; }
        int o = (ib + tid) * NSPLIT + blockIdx.y;
        g_pv[o] = pv; g_pi[o] = pi; g_nv[o] = nv; g_ni[o] = ni;
    }
}

// ---------------- K3: merge splits, gather triplets, partial sums ----------------
__global__ void terms_kernel(const float* __restrict__ x, const int* __restrict__ tg) {
    __shared__ float red[4 * 9];
    int tid = threadIdx.x;
    int lane = tid & 31, wrp = tid >> 5;
    int row = blockIdx.x * 128 + tid;

    float pv = -FLT_MAX, nv = FLT_MAX;
    int gp = NN, gn = NN;
    #pragma unroll
    for (int s2 = 0; s2 < NSPLIT; s2++) {
        int o = row * NSPLIT + s2;
        float v = g_pv[o]; int id = g_pi[o];
        if (v > pv || (v == pv && id < gp)) { pv = v; gp = id; }
        v = g_nv[o]; id = g_ni[o];
        if (v < nv || (v == nv && id < gn)) { nv = v; gn = id; }
    }
    int t = tg[row];
    int cs = g_hist[t];
    float vf = (cs > 1 && (NN - cs) >= 1) ? 1.0f : 0.0f;
    gp = min(max(gp, 0), NN - 1);
    gn = min(max(gn, 0), NN - 1);
    int ppos = g_ps[t * NN + gp] - 1;
    int pneg = gn - g_ps[t * NN + gn];
    ppos = min(max(ppos, 0), NN - 1);
    pneg = min(max(pneg, 0), NN - 1);

    const float4* A = reinterpret_cast<const float4*>(x) + (size_t)row * 32;
    const float4* P = reinterpret_cast<const float4*>(x) + (size_t)ppos * 32;
    const float4* Q = reinterpret_cast<const float4*>(x) + (size_t)pneg * 32;
    float ap = 0, an = 0, npd = 0, l1a = 0, l1p = 0, l1n = 0;
    #pragma unroll
    for (int q = 0; q < 32; q++) {
        float4 a = A[q], p = P[q], n = Q[q];
        float d;
        d = a.x - p.x; ap = fmaf(d, d, ap);
        d = a.y - p.y; ap = fmaf(d, d, ap);
        d = a.z - p.z; ap = fmaf(d, d, ap);
        d = a.w - p.w; ap = fmaf(d, d, ap);
        d = a.x - n.x; an = fmaf(d, d, an);
        d = a.y - n.y; an = fmaf(d, d, an);
        d = a.z - n.z; an = fmaf(d, d, an);
        d = a.w - n.w; an = fmaf(d, d, an);
        d = p.x - n.x; npd = fmaf(d, d, npd);
        d = p.y - n.y; npd = fmaf(d, d, npd);
        d = p.z - n.z; npd = fmaf(d, d, npd);
        d = p.w - n.w; npd = fmaf(d, d, npd);
        l1a += fabsf(a.x) + fabsf(a.y) + fabsf(a.z) + fabsf(a.w);
        l1p += fabsf(p.x) + fabsf(p.y) + fabsf(p.z) + fabsf(p.w);
        l1n += fabsf(n.x) + fabsf(n.y) + fabsf(n.z) + fabsf(n.w);
    }
    float tl = fmaxf(ap - an + FMARGIN, 0.0f) * vf;

    float vals[9];
    vals[0] = tl;
    vals[1] = (tl > 0.0f) ? 1.0f : 0.0f;
    vals[2] = l1a * vf;
    vals[3] = l1p * vf;
    vals[4] = l1n * vf;
    vals[5] = ap * vf;
    vals[6] = an * vf;
    vals[7] = (ap - an - npd) * vf;
    vals[8] = vf;

    #pragma unroll
    for (int k = 0; k < 9; k++) {
        float v = vals[k];
        #pragma unroll
        for (int o = 16; o > 0; o >>= 1) v += __shfl_down_sync(0xffffffffu, v, o);
        if (lane == 0) red[wrp * 9 + k] = v;
    }
    __syncthreads();
    if (tid < 9)
        g_part[blockIdx.x * 9 + tid] = red[tid] + red[9 + tid] + red[18 + tid] + red[27 + tid];
}

// ---------------- K4: finalize ----------------
__global__ void final_kernel(float* __restrict__ out, int out_size) {
    __shared__ float r[6];
    if (threadIdx.x == 0) {
        float s[9];
        for (int k = 0; k < 9; k++) s[k] = 0.0f;
        for (int b = 0; b < 64; b++)
            for (int k = 0; k < 9; k++) s[k] += g_part[b * 9 + k];
        float vcount = s[8];
        float inv = (vcount > 0.0f) ? (1.0f / vcount) : 0.0f;
        float trip = (s[1] > 0.0f) ? (s[0] / s[1]) : (s[0] * inv);
        float sparse = (s[2] + s[3] + s[4]) * inv * (1.0f / 3.0f);
        float pw = s[7] * inv;
        if (pw < 0.0f) pw = 0.0f;
        r[0] = trip; r[1] = sparse; r[2] = pw;
        r[3] = vcount; r[4] = s[5] * inv; r[5] = s[6] * inv;
    }
    __syncthreads();
    for (int i = threadIdx.x; i < out_size; i += blockDim.x)
        out[i] = (i < 6) ? r[i] : 0.0f;
}

// ---------------- launch ----------------
extern "C" void kernel_launch(void* const* d_in, const int* in_sizes, int n_in,
                              void* d_out, int out_size) {
    const float* x = (const float*)d_in[0];
    const int* tg = (const int*)d_in[1];

    const int smem_bytes = W_TOT * 4;    // 213504
    cudaFuncSetAttribute(dist_mma_kernel, cudaFuncAttributeMaxDynamicSharedMemorySize,
                         smem_bytes);

    prep_kernel<<<64, 128>>>(x);
    prefix_kernel<<<CC, 256>>>(tg);
    dist_mma_kernel<<<dim3(NN / BI, NSPLIT), 256, smem_bytes>>>(tg);
    terms_kernel<<<64, 128>>>(x, tg);
    final_kernel<<<1, 64>>>((float*)d_out, out_size);
}

// round 5
// speedup vs baseline: 2.2394x; 2.1304x over previous
#include <cuda_runtime.h>
#include <cuda_fp16.h>
#include <cfloat>
#include <cstdint>

#define NN 8192
#define DD 128
#define CC 64
#define FMARGIN 0.5f
#define NSPLIT 2
#define JSPAN (NN / NSPLIT)     // 4096
#define BI 128
#define BJ 64
#define NTILES (JSPAN / BJ)     // 64

// smem byte offsets
#define S_AHI 0                 // 128 rows x 256B (swizzled)
#define S_ALO 32768
#define S_BHI 65536             // 2 bufs x 64 rows x 256B
#define S_BLO 98304
#define S_MXN 131072            // 2 bufs x 64 f32
#define S_MTG 131584            // 2 bufs x 64 i32
#define S_MPV 132096            // 2*128 f32
#define S_MPI 133120
#define S_MNV 134144
#define S_MNI 135168
#define S_TOT 136192

// ---------------- device scratch ----------------
__device__ __half g_h16[NN * DD];
__device__ __half g_l16[NN * DD];
__device__ float g_xn[NN];
__device__ int   g_ps[CC * NN];
__device__ int   g_hist[CC];
__device__ float g_pv[NN * NSPLIT];
__device__ int   g_pi[NN * NSPLIT];
__device__ float g_nv[NN * NSPLIT];
__device__ int   g_ni[NN * NSPLIT];
__device__ float g_part[64 * 9];

// ---------------- PTX helpers ----------------
__device__ __forceinline__ uint32_t smem_u32(const void* p) {
    uint32_t a;
    asm("{ .reg .u64 t; cvta.to.shared.u64 t, %1; cvt.u32.u64 %0, t; }" : "=r"(a) : "l"(p));
    return a;
}
__device__ __forceinline__ uint64_t gbl_u64(const void* p) {
    uint64_t a;
    asm("cvta.to.global.u64 %0, %1;" : "=l"(a) : "l"(p));
    return a;
}
__device__ __forceinline__ void cpa16(uint32_t dst, uint64_t src) {
    asm volatile("cp.async.cg.shared.global [%0], [%1], 16;" :: "r"(dst), "l"(src));
}
__device__ __forceinline__ void cpa4(uint32_t dst, uint64_t src) {
    asm volatile("cp.async.ca.shared.global [%0], [%1], 4;" :: "r"(dst), "l"(src));
}
#define CPA_COMMIT() asm volatile("cp.async.commit_group;" ::: "memory")
#define CPA_WAIT0()  asm volatile("cp.async.wait_group 0;" ::: "memory")

__device__ __forceinline__ void ldsm4(uint32_t* r, uint32_t addr) {
    asm volatile("ldmatrix.sync.aligned.m8n8.x4.shared.b16 {%0,%1,%2,%3}, [%4];"
                 : "=r"(r[0]), "=r"(r[1]), "=r"(r[2]), "=r"(r[3]) : "r"(addr));
}
__device__ __forceinline__ void mma_f16(float* d, const uint32_t* a, uint32_t b0, uint32_t b1) {
    asm volatile(
        "mma.sync.aligned.m16n8k16.row.col.f32.f16.f16.f32 "
        "{%0,%1,%2,%3}, {%4,%5,%6,%7}, {%8,%9}, {%0,%1,%2,%3};"
        : "+f"(d[0]), "+f"(d[1]), "+f"(d[2]), "+f"(d[3])
        : "r"(a[0]), "r"(a[1]), "r"(a[2]), "r"(a[3]), "r"(b0), "r"(b1));
}

// ---------------- K0: fp16 split + norms ----------------
__global__ void prep_kernel(const float* __restrict__ x) {
    int row = blockIdx.x * blockDim.x + threadIdx.x;
    const float4* xr = reinterpret_cast<const float4*>(x) + (size_t)row * 32;
    __half2* hr = reinterpret_cast<__half2*>(g_h16) + (size_t)row * 64;
    __half2* lr = reinterpret_cast<__half2*>(g_l16) + (size_t)row * 64;
    float s = 0.0f;
    #pragma unroll
    for (int q = 0; q < 32; q++) {
        float4 v = xr[q];
        __half hx = __float2half_rn(v.x), hy = __float2half_rn(v.y);
        __half hz = __float2half_rn(v.z), hw = __float2half_rn(v.w);
        float lx = v.x - __half2float(hx), ly = v.y - __half2float(hy);
        float lz = v.z - __half2float(hz), lw = v.w - __half2float(hw);
        hr[2 * q + 0] = __halves2half2(hx, hy);
        hr[2 * q + 1] = __halves2half2(hz, hw);
        lr[2 * q + 0] = __halves2half2(__float2half_rn(lx), __float2half_rn(ly));
        lr[2 * q + 1] = __halves2half2(__float2half_rn(lz), __float2half_rn(lw));
        s = fmaf(v.x, v.x, s); s = fmaf(v.y, v.y, s);
        s = fmaf(v.z, v.z, s); s = fmaf(v.w, v.w, s);
    }
    g_xn[row] = s;
}

// ---------------- K1: per-class inclusive prefix counts ----------------
__global__ void prefix_kernel(const int* __restrict__ tg) {
    int c = blockIdx.x;
    __shared__ int wsum[8];
    __shared__ int wpre[8];
    __shared__ int stot;
    int lane = threadIdx.x & 31, wid = threadIdx.x >> 5;
    int run = 0;
    for (int base = 0; base < NN; base += 256) {
        int f = (tg[base + threadIdx.x] == c) ? 1 : 0;
        int s = f;
        #pragma unroll
        for (int o = 1; o < 32; o <<= 1) {
            int v = __shfl_up_sync(0xffffffffu, s, o);
            if (lane >= o) s += v;
        }
        if (lane == 31) wsum[wid] = s;
        __syncthreads();
        if (threadIdx.x == 0) {
            int a = 0;
            for (int w = 0; w < 8; w++) { wpre[w] = a; a += wsum[w]; }
            stot = a;
        }
        __syncthreads();
        g_ps[c * NN + base + threadIdx.x] = run + wpre[wid] + s;
        run += stot;
        __syncthreads();
    }
    if (threadIdx.x == 0) g_hist[c] = run;
}

// ---------------- K2: fp16-split mma.sync masked argmax/argmin ----------------
__global__ void __launch_bounds__(256, 1)
dist_mma_kernel(const int* __restrict__ tg) {
    extern __shared__ char sm[];
    const uint32_t sb = smem_u32(sm);
    const uint64_t GH = gbl_u64(g_h16);
    const uint64_t GL = gbl_u64(g_l16);
    const uint64_t GX = gbl_u64(g_xn);
    const uint64_t GT = gbl_u64(tg);

    const int tid = threadIdx.x;
    const int lane = tid & 31;
    const int wid = tid >> 5;
    const int wm = wid >> 1;             // 0..3
    const int wn = wid & 1;              // 0..1
    const int tq = lane & 3;
    const int rg = lane >> 2;            // 0..7
    const int ib = blockIdx.x * BI;
    const int jb0 = blockIdx.y * JSPAN;

    // ldmatrix per-lane addressing constants
    const uint32_t x7 = lane & 7;
    const uint32_t ahit = lane >> 4;              // A chunk increment
    const uint32_t bhit = (lane >> 3) & 1;        // B chunk increment
    const uint32_t arow0 = wm * 32 + (lane & 15);
    const uint32_t arow1 = arow0 + 16;
    const uint32_t brow0 = wn * 32 + (lane & 7) + ((lane >> 4) << 3);
    const uint32_t brow1 = brow0 + 16;

    // ---- initial prefetch: A tile (hi+lo), B tile 0, meta 0 ----
    #pragma unroll
    for (int u = 0; u < 16; u++) {
        int idx = tid + u * 256;                  // 0..4095
        int comp = idx >> 11, rem = idx & 2047;
        int r = rem >> 4, kc = rem & 15;
        uint64_t src = (comp ? GL : GH) + (((size_t)(ib + r) * DD + kc * 8) << 1);
        uint32_t dst = sb + (comp ? S_ALO : S_AHI) + r * 256 + ((kc ^ (r & 7)) << 4);
        cpa16(dst, src);
    }
    #pragma unroll
    for (int u = 0; u < 8; u++) {
        int idx = tid + u * 256;                  // 0..2047
        int comp = idx >> 10, rem = idx & 1023;
        int r = rem >> 4, kc = rem & 15;
        uint64_t src = (comp ? GL : GH) + (((size_t)(jb0 + r) * DD + kc * 8) << 1);
        uint32_t dst = sb + (comp ? S_BLO : S_BHI) + r * 256 + ((kc ^ (r & 7)) << 4);
        cpa16(dst, src);
    }
    if (tid < 64)       cpa4(sb + S_MXN + tid * 4, GX + (size_t)(jb0 + tid) * 4);
    else if (tid < 128) cpa4(sb + S_MTG + (tid - 64) * 4, GT + (size_t)(jb0 + tid - 64) * 4);
    CPA_COMMIT();

    // row-state: 4 owned rows per thread (m, h)
    float bpv[4], bnv[4];
    int bpi[4], bni[4], ti_[4];
    #pragma unroll
    for (int r = 0; r < 4; r++) {
        bpv[r] = -FLT_MAX; bnv[r] = FLT_MAX; bpi[r] = NN; bni[r] = NN;
        ti_[r] = tg[ib + wm * 32 + (r >> 1) * 16 + (r & 1) * 8 + rg];
    }
    float acc[2][4][4];
    #pragma unroll
    for (int m = 0; m < 2; m++)
        #pragma unroll
        for (int n = 0; n < 4; n++)
            #pragma unroll
            for (int c = 0; c < 4; c++) acc[m][n][c] = 0.0f;

    CPA_WAIT0();
    __syncthreads();

    for (int t = 0; t < NTILES; t++) {
        const int buf = t & 1;
        const int jb = jb0 + t * BJ;

        // prefetch tile t+1
        if (t + 1 < NTILES) {
            const int nb = (t + 1) & 1;
            const int jn = jb + BJ;
            #pragma unroll
            for (int u = 0; u < 8; u++) {
                int idx = tid + u * 256;
                int comp = idx >> 10, rem = idx & 1023;
                int r = rem >> 4, kc = rem & 15;
                uint64_t src = (comp ? GL : GH) + (((size_t)(jn + r) * DD + kc * 8) << 1);
                uint32_t dst = sb + (comp ? S_BLO : S_BHI) + nb * 16384
                             + r * 256 + ((kc ^ (r & 7)) << 4);
                cpa16(dst, src);
            }
            if (tid < 64)       cpa4(sb + S_MXN + nb * 256 + tid * 4, GX + (size_t)(jn + tid) * 4);
            else if (tid < 128) cpa4(sb + S_MTG + nb * 256 + (tid - 64) * 4, GT + (size_t)(jn + tid - 64) * 4);
            CPA_COMMIT();
        }

        // ---- compute: 8 k-steps, 3 fused passes ----
        const uint32_t bhb = sb + S_BHI + buf * 16384;
        const uint32_t blb = sb + S_BLO + buf * 16384;
        #pragma unroll
        for (int ks = 0; ks < 8; ks++) {
            uint32_t ah[2][4], al[2][4], bh[2][4], bl[2][4];
            const uint32_t swzA = (((uint32_t)(2 * ks) + ahit) ^ x7) << 4;
            const uint32_t swzB = (((uint32_t)(2 * ks) + bhit) ^ x7) << 4;
            ldsm4(ah[0], sb + S_AHI + arow0 * 256 + swzA);
            ldsm4(ah[1], sb + S_AHI + arow1 * 256 + swzA);
            ldsm4(al[0], sb + S_ALO + arow0 * 256 + swzA);
            ldsm4(al[1], sb + S_ALO + arow1 * 256 + swzA);
            ldsm4(bh[0], bhb + brow0 * 256 + swzB);
            ldsm4(bh[1], bhb + brow1 * 256 + swzB);
            ldsm4(bl[0], blb + brow0 * 256 + swzB);
            ldsm4(bl[1], blb + brow1 * 256 + swzB);
            #pragma unroll
            for (int m = 0; m < 2; m++) {
                #pragma unroll
                for (int n = 0; n < 4; n++) {
                    const int ng = n >> 1, p = (n & 1) * 2;
                    mma_f16(acc[m][n], ah[m], bh[ng][p], bh[ng][p + 1]);  // hi*hi
                    mma_f16(acc[m][n], ah[m], bl[ng][p], bl[ng][p + 1]);  // hi*lo
                    mma_f16(acc[m][n], al[m], bh[ng][p], bh[ng][p + 1]);  // lo*hi
                }
            }
        }

        // ---- epilogue: scores + running masked argmax/argmin, reset acc ----
        const float* sxn = reinterpret_cast<const float*>(sm + S_MXN) + buf * 64;
        const int* stg = reinterpret_cast<const int*>(sm + S_MTG) + buf * 64;
        #pragma unroll
        for (int n = 0; n < 4; n++) {
            const int c0 = wn * 32 + n * 8 + 2 * tq;
            const float xn0 = sxn[c0], xn1 = sxn[c0 + 1];
            const int tg0 = stg[c0], tg1 = stg[c0 + 1];
            const int j0 = jb + c0;
            #pragma unroll
            for (int m = 0; m < 2; m++) {
                #pragma unroll
                for (int h = 0; h < 2; h++) {
                    const int ri = m * 2 + h;
                    float s0 = fmaf(-2.0f, acc[m][n][h * 2 + 0], xn0);
                    float s1 = fmaf(-2.0f, acc[m][n][h * 2 + 1], xn1);
                    if (tg0 == ti_[ri]) {
                        if (s0 > bpv[ri]) { bpv[ri] = s0; bpi[ri] = j0; }
                    } else {
                        if (s0 < bnv[ri]) { bnv[ri] = s0; bni[ri] = j0; }
                    }
                    if (tg1 == ti_[ri]) {
                        if (s1 > bpv[ri]) { bpv[ri] = s1; bpi[ri] = j0 + 1; }
                    } else {
                        if (s1 < bnv[ri]) { bnv[ri] = s1; bni[ri] = j0 + 1; }
                    }
                    acc[m][n][h * 2 + 0] = 0.0f;
                    acc[m][n][h * 2 + 1] = 0.0f;
                }
            }
        }

        CPA_WAIT0();
        __syncthreads();
    }

    // ---- merge: tq lanes (disjoint cols, same rows) ----
    #pragma unroll
    for (int r = 0; r < 4; r++) {
        #pragma unroll
        for (int off = 1; off <= 2; off <<= 1) {
            float ov = __shfl_xor_sync(0xffffffffu, bpv[r], off);
            int oi = __shfl_xor_sync(0xffffffffu, bpi[r], off);
            if (ov > bpv[r] || (ov == bpv[r] && oi < bpi[r])) { bpv[r] = ov; bpi[r] = oi; }
            ov = __shfl_xor_sync(0xffffffffu, bnv[r], off);
            oi = __shfl_xor_sync(0xffffffffu, bni[r], off);
            if (ov < bnv[r] || (ov == bnv[r] && oi < bni[r])) { bnv[r] = ov; bni[r] = oi; }
        }
    }
    float* mpv = reinterpret_cast<float*>(sm + S_MPV);
    int* mpi = reinterpret_cast<int*>(sm + S_MPI);
    float* mnv = reinterpret_cast<float*>(sm + S_MNV);
    int* mni = reinterpret_cast<int*>(sm + S_MNI);
    if (tq == 0) {
        #pragma unroll
        for (int r = 0; r < 4; r++) {
            int row = wm * 32 + (r >> 1) * 16 + (r & 1) * 8 + rg;
            mpv[wn * 128 + row] = bpv[r]; mpi[wn * 128 + row] = bpi[r];
            mnv[wn * 128 + row] = bnv[r]; mni[wn * 128 + row] = bni[r];
        }
    }
    __syncthreads();
    if (tid < 128) {
        float pv = mpv[tid]; int pi = mpi[tid];
        float v = mpv[128 + tid]; int id = mpi[128 + tid];
        if (v > pv || (v == pv && id < pi)) { pv = v; pi = id; }
        float nv = mnv[tid]; int ni = mni[tid];
        v = mnv[128 + tid]; id = mni[128 + tid];
        if (v < nv || (v == nv && id < ni)) { nv = v; ni = id; }
        int o = (ib + tid) * NSPLIT + blockIdx.y;
        g_pv[o] = pv; g_pi[o] = pi; g_nv[o] = nv; g_ni[o] = ni;
    }
}

// ---------------- K3: merge splits, gather triplets, partial sums ----------------
__global__ void terms_kernel(const float* __restrict__ x, const int* __restrict__ tg) {
    __shared__ float red[4 * 9];
    int tid = threadIdx.x;
    int lane = tid & 31, wrp = tid >> 5;
    int row = blockIdx.x * 128 + tid;

    float pv = -FLT_MAX, nv = FLT_MAX;
    int gp = NN, gn = NN;
    #pragma unroll
    for (int s2 = 0; s2 < NSPLIT; s2++) {
        int o = row * NSPLIT + s2;
        float v = g_pv[o]; int id = g_pi[o];
        if (v > pv || (v == pv && id < gp)) { pv = v; gp = id; }
        v = g_nv[o]; id = g_ni[o];
        if (v < nv || (v == nv && id < gn)) { nv = v; gn = id; }
    }
    int t = tg[row];
    int cs = g_hist[t];
    float vf = (cs > 1 && (NN - cs) >= 1) ? 1.0f : 0.0f;
    gp = min(max(gp, 0), NN - 1);
    gn = min(max(gn, 0), NN - 1);
    int ppos = g_ps[t * NN + gp] - 1;
    int pneg = gn - g_ps[t * NN + gn];
    ppos = min(max(ppos, 0), NN - 1);
    pneg = min(max(pneg, 0), NN - 1);

    const float4* A = reinterpret_cast<const float4*>(x) + (size_t)row * 32;
    const float4* P = reinterpret_cast<const float4*>(x) + (size_t)ppos * 32;
    const float4* Q = reinterpret_cast<const float4*>(x) + (size_t)pneg * 32;
    float ap = 0, an = 0, npd = 0, l1a = 0, l1p = 0, l1n = 0;
    #pragma unroll
    for (int q = 0; q < 32; q++) {
        float4 a = A[q], p = P[q], n = Q[q];
        float d;
        d = a.x - p.x; ap = fmaf(d, d, ap);
        d = a.y - p.y; ap = fmaf(d, d, ap);
        d = a.z - p.z; ap = fmaf(d, d, ap);
        d = a.w - p.w; ap = fmaf(d, d, ap);
        d = a.x - n.x; an = fmaf(d, d, an);
        d = a.y - n.y; an = fmaf(d, d, an);
        d = a.z - n.z; an = fmaf(d, d, an);
        d = a.w - n.w; an = fmaf(d, d, an);
        d = p.x - n.x; npd = fmaf(d, d, npd);
        d = p.y - n.y; npd = fmaf(d, d, npd);
        d = p.z - n.z; npd = fmaf(d, d, npd);
        d = p.w - n.w; npd = fmaf(d, d, npd);
        l1a += fabsf(a.x) + fabsf(a.y) + fabsf(a.z) + fabsf(a.w);
        l1p += fabsf(p.x) + fabsf(p.y) + fabsf(p.z) + fabsf(p.w);
        l1n += fabsf(n.x) + fabsf(n.y) + fabsf(n.z) + fabsf(n.w);
    }
    float tl = fmaxf(ap - an + FMARGIN, 0.0f) * vf;

    float vals[9];
    vals[0] = tl;
    vals[1] = (tl > 0.0f) ? 1.0f : 0.0f;
    vals[2] = l1a * vf;
    vals[3] = l1p * vf;
    vals[4] = l1n * vf;
    vals[5] = ap * vf;
    vals[6] = an * vf;
    vals[7] = (ap - an - npd) * vf;
    vals[8] = vf;

    #pragma unroll
    for (int k = 0; k < 9; k++) {
        float v = vals[k];
        #pragma unroll
        for (int o = 16; o > 0; o >>= 1) v += __shfl_down_sync(0xffffffffu, v, o);
        if (lane == 0) red[wrp * 9 + k] = v;
    }
    __syncthreads();
    if (tid < 9)
        g_part[blockIdx.x * 9 + tid] = red[tid] + red[9 + tid] + red[18 + tid] + red[27 + tid];
}

// ---------------- K4: finalize ----------------
__global__ void final_kernel(float* __restrict__ out, int out_size) {
    __shared__ float r[6];
    if (threadIdx.x == 0) {
        float s[9];
        for (int k = 0; k < 9; k++) s[k] = 0.0f;
        for (int b = 0; b < 64; b++)
            for (int k = 0; k < 9; k++) s[k] += g_part[b * 9 + k];
        float vcount = s[8];
        float inv = (vcount > 0.0f) ? (1.0f / vcount) : 0.0f;
        float trip = (s[1] > 0.0f) ? (s[0] / s[1]) : (s[0] * inv);
        float sparse = (s[2] + s[3] + s[4]) * inv * (1.0f / 3.0f);
        float pw = s[7] * inv;
        if (pw < 0.0f) pw = 0.0f;
        r[0] = trip; r[1] = sparse; r[2] = pw;
        r[3] = vcount; r[4] = s[5] * inv; r[5] = s[6] * inv;
    }
    __syncthreads();
    for (int i = threadIdx.x; i < out_size; i += blockDim.x)
        out[i] = (i < 6) ? r[i] : 0.0f;
}

// ---------------- launch ----------------
extern "C" void kernel_launch(void* const* d_in, const int* in_sizes, int n_in,
                              void* d_out, int out_size) {
    const float* x = (const float*)d_in[0];
    const int* tg = (const int*)d_in[1];

    cudaFuncSetAttribute(dist_mma_kernel, cudaFuncAttributeMaxDynamicSharedMemorySize,
                         S_TOT);

    prep_kernel<<<64, 128>>>(x);
    prefix_kernel<<<CC, 256>>>(tg);
    dist_mma_kernel<<<dim3(NN / BI, NSPLIT), 256, S_TOT>>>(tg);
    terms_kernel<<<64, 128>>>(x, tg);
    final_kernel<<<1, 64>>>((float*)d_out, out_size);
}

// round 6
// speedup vs baseline: 2.2424x; 1.0013x over previous
#include <cuda_runtime.h>
#include <cuda_fp16.h>
#include <cfloat>
#include <cstdint>

#define NN 8192
#define DD 128
#define CC 64
#define FMARGIN 0.5f
#define NB 64                      // 128-row blocks
#define NPAIRS (NB * (NB + 1) / 2) // 2080

// smem byte offsets
#define S_AHI 0                    // 128 x 256B swizzled
#define S_ALO 32768
#define S_BHI 65536
#define S_BLO 98304
#define S_XNA 131072               // 128 f32
#define S_TGA 131584
#define S_XNB 132096
#define S_TGB 132608
#define S_RPV 133120               // 2 x 128 f32
#define S_RPI 134144
#define S_RNV 135168
#define S_RNI 136192
#define S_CPV 137216               // 4 x 128 f32
#define S_CPI 139264
#define S_CNV 141312
#define S_CNI 143360
#define S_TOT 145408

// ---------------- device scratch ----------------
__device__ __half g_h16[NN * DD];
__device__ __half g_l16[NN * DD];
__device__ float g_xn[NN];
__device__ int   g_ps[CC * NN];
__device__ int   g_hist[CC];
__device__ float g_pv[(size_t)NN * NB];
__device__ int   g_pi[(size_t)NN * NB];
__device__ float g_nv[(size_t)NN * NB];
__device__ int   g_ni[(size_t)NN * NB];
__device__ float g_part[64 * 9];

// ---------------- PTX helpers ----------------
__device__ __forceinline__ uint32_t smem_u32(const void* p) {
    uint32_t a;
    asm("{ .reg .u64 t; cvta.to.shared.u64 t, %1; cvt.u32.u64 %0, t; }" : "=r"(a) : "l"(p));
    return a;
}
__device__ __forceinline__ uint64_t gbl_u64(const void* p) {
    uint64_t a;
    asm("cvta.to.global.u64 %0, %1;" : "=l"(a) : "l"(p));
    return a;
}
__device__ __forceinline__ void cpa16(uint32_t dst, uint64_t src) {
    asm volatile("cp.async.cg.shared.global [%0], [%1], 16;" :: "r"(dst), "l"(src));
}
__device__ __forceinline__ void cpa4(uint32_t dst, uint64_t src) {
    asm volatile("cp.async.ca.shared.global [%0], [%1], 4;" :: "r"(dst), "l"(src));
}
#define CPA_COMMIT() asm volatile("cp.async.commit_group;" ::: "memory")
#define CPA_WAIT(n)  asm volatile("cp.async.wait_group %0;" :: "n"(n) : "memory")

__device__ __forceinline__ void ldsm4(uint32_t* r, uint32_t addr) {
    asm volatile("ldmatrix.sync.aligned.m8n8.x4.shared.b16 {%0,%1,%2,%3}, [%4];"
                 : "=r"(r[0]), "=r"(r[1]), "=r"(r[2]), "=r"(r[3]) : "r"(addr));
}
__device__ __forceinline__ void mma_f16(float* d, const uint32_t* a, uint32_t b0, uint32_t b1) {
    asm volatile(
        "mma.sync.aligned.m16n8k16.row.col.f32.f16.f16.f32 "
        "{%0,%1,%2,%3}, {%4,%5,%6,%7}, {%8,%9}, {%0,%1,%2,%3};"
        : "+f"(d[0]), "+f"(d[1]), "+f"(d[2]), "+f"(d[3])
        : "r"(a[0]), "r"(a[1]), "r"(a[2]), "r"(a[3]), "r"(b0), "r"(b1));
}

// ---------------- K0: fp16 split + norms ----------------
__global__ void prep_kernel(const float* __restrict__ x) {
    int row = blockIdx.x * blockDim.x + threadIdx.x;
    const float4* xr = reinterpret_cast<const float4*>(x) + (size_t)row * 32;
    __half2* hr = reinterpret_cast<__half2*>(g_h16) + (size_t)row * 64;
    __half2* lr = reinterpret_cast<__half2*>(g_l16) + (size_t)row * 64;
    float s = 0.0f;
    #pragma unroll
    for (int q = 0; q < 32; q++) {
        float4 v = xr[q];
        __half hx = __float2half_rn(v.x), hy = __float2half_rn(v.y);
        __half hz = __float2half_rn(v.z), hw = __float2half_rn(v.w);
        float lx = v.x - __half2float(hx), ly = v.y - __half2float(hy);
        float lz = v.z - __half2float(hz), lw = v.w - __half2float(hw);
        hr[2 * q + 0] = __halves2half2(hx, hy);
        hr[2 * q + 1] = __halves2half2(hz, hw);
        lr[2 * q + 0] = __halves2half2(__float2half_rn(lx), __float2half_rn(ly));
        lr[2 * q + 1] = __halves2half2(__float2half_rn(lz), __float2half_rn(lw));
        s = fmaf(v.x, v.x, s); s = fmaf(v.y, v.y, s);
        s = fmaf(v.z, v.z, s); s = fmaf(v.w, v.w, s);
    }
    g_xn[row] = s;
}

// ---------------- K1: per-class inclusive prefix counts ----------------
__global__ void prefix_kernel(const int* __restrict__ tg) {
    int c = blockIdx.x;
    __shared__ int wsum[8];
    __shared__ int wpre[8];
    __shared__ int stot;
    int lane = threadIdx.x & 31, wid = threadIdx.x >> 5;
    int run = 0;
    for (int base = 0; base < NN; base += 256) {
        int f = (tg[base + threadIdx.x] == c) ? 1 : 0;
        int s = f;
        #pragma unroll
        for (int o = 1; o < 32; o <<= 1) {
            int v = __shfl_up_sync(0xffffffffu, s, o);
            if (lane >= o) s += v;
        }
        if (lane == 31) wsum[wid] = s;
        __syncthreads();
        if (threadIdx.x == 0) {
            int a = 0;
            for (int w = 0; w < 8; w++) { wpre[w] = a; a += wsum[w]; }
            stot = a;
        }
        __syncthreads();
        g_ps[c * NN + base + threadIdx.x] = run + wpre[wid] + s;
        run += stot;
        __syncthreads();
    }
    if (threadIdx.x == 0) g_hist[c] = run;
}

// ---------------- K2: triangular symmetric fp16-split mma tile ----------------
// One CTA per block pair (bi <= bj). 128x128 tile, folded both directions.
__global__ void __launch_bounds__(256, 1)
dist_mma_kernel(const int* __restrict__ tg) {
    extern __shared__ char sm[];
    const uint32_t sb = smem_u32(sm);
    const uint64_t GH = gbl_u64(g_h16);
    const uint64_t GL = gbl_u64(g_l16);
    const uint64_t GX = gbl_u64(g_xn);
    const uint64_t GT = gbl_u64(tg);

    // map blockIdx.x -> (bi, bj), bi <= bj
    int tt = blockIdx.x, bi = 0;
    while (tt >= NB - bi) { tt -= NB - bi; bi++; }
    const int bj = bi + tt;
    const int ib = bi * 128, jb = bj * 128;
    const bool diag = (bi == bj);

    const int tid = threadIdx.x;
    const int lane = tid & 31;
    const int wid = tid >> 5;
    const int wm = wid >> 1;             // 0..3 row group (32 rows)
    const int wn = wid & 1;              // 0..1 col group (64 cols)
    const int tq = lane & 3;
    const int rg = lane >> 2;
    const uint32_t x7 = lane & 7;
    const uint32_t ahit = lane >> 4;
    const uint32_t bhit = (lane >> 3) & 1;

    // ---- loads: group0 = k-half0 (all 4 tiles) + meta; group1 = k-half1 ----
    #pragma unroll
    for (int h = 0; h < 2; h++) {
        #pragma unroll
        for (int u = 0; u < 16; u++) {
            int idx = tid + u * 256;             // 0..4095
            int comp = idx >> 10;                // 0 Ahi, 1 Alo, 2 Bhi, 3 Blo
            int rem = idx & 1023;
            int r = rem >> 3;
            int kc = h * 8 + (rem & 7);
            uint64_t garr = (comp & 1) ? GL : GH;
            int base = (comp & 2) ? jb : ib;
            uint32_t sbase = (comp == 0) ? S_AHI : (comp == 1) ? S_ALO
                           : (comp == 2) ? S_BHI : S_BLO;
            uint64_t src = garr + (((size_t)(base + r) * DD + kc * 8) << 1);
            uint32_t dst = sb + sbase + r * 256 + (((uint32_t)kc ^ (r & 7)) << 4);
            cpa16(dst, src);
        }
        if (h == 0) {
            #pragma unroll
            for (int v = 0; v < 2; v++) {
                int id2 = tid + v * 256;         // 0..511
                int arr = id2 >> 7, e = id2 & 127;
                uint64_t src = (arr == 0) ? GX + ((size_t)(ib + e) << 2)
                             : (arr == 1) ? GT + ((size_t)(ib + e) << 2)
                             : (arr == 2) ? GX + ((size_t)(jb + e) << 2)
                                          : GT + ((size_t)(jb + e) << 2);
                cpa4(sb + S_XNA + arr * 512 + e * 4, src);
            }
        }
        CPA_COMMIT();
    }

    float acc[2][8][4];
    #pragma unroll
    for (int mi = 0; mi < 2; mi++)
        #pragma unroll
        for (int ni = 0; ni < 8; ni++)
            #pragma unroll
            for (int c = 0; c < 4; c++) acc[mi][ni][c] = 0.0f;

    const uint32_t arow0 = wm * 32 + (lane & 15);
    const uint32_t arow1 = arow0 + 16;

    CPA_WAIT(1);
    __syncthreads();

    // ---- compute: 8 k-steps (k16), 3 fused passes; half1 wait at ks==4 ----
    #pragma unroll
    for (int ks = 0; ks < 8; ks++) {
        if (ks == 4) {
            CPA_WAIT(0);
            __syncthreads();
        }
        uint32_t ah[2][4], al[2][4], bh[4][4], bl[4][4];
        const uint32_t swzA = (((uint32_t)(2 * ks) + ahit) ^ x7) << 4;
        const uint32_t swzB = (((uint32_t)(2 * ks) + bhit) ^ x7) << 4;
        ldsm4(ah[0], sb + S_AHI + arow0 * 256 + swzA);
        ldsm4(ah[1], sb + S_AHI + arow1 * 256 + swzA);
        ldsm4(al[0], sb + S_ALO + arow0 * 256 + swzA);
        ldsm4(al[1], sb + S_ALO + arow1 * 256 + swzA);
        #pragma unroll
        for (int q = 0; q < 4; q++) {
            uint32_t brow = wn * 64 + q * 16 + x7 + (ahit << 3);
            ldsm4(bh[q], sb + S_BHI + brow * 256 + swzB);
            ldsm4(bl[q], sb + S_BLO + brow * 256 + swzB);
        }
        #pragma unroll
        for (int mi = 0; mi < 2; mi++) {
            #pragma unroll
            for (int ni = 0; ni < 8; ni++) {
                const int q = ni >> 1, p = (ni & 1) * 2;
                mma_f16(acc[mi][ni], ah[mi], bh[q][p], bh[q][p + 1]);  // hi*hi
                mma_f16(acc[mi][ni], ah[mi], bl[q][p], bl[q][p + 1]);  // hi*lo
                mma_f16(acc[mi][ni], al[mi], bh[q][p], bh[q][p + 1]);  // lo*hi
            }
        }
    }

    // ---- epilogue: fold both directions ----
    const float* sXNA = (const float*)(sm + S_XNA);
    const int*   sTGA = (const int*)(sm + S_TGA);
    const float* sXNB = (const float*)(sm + S_XNB);
    const int*   sTGB = (const int*)(sm + S_TGB);

    float xna[4]; int tga[4];
    #pragma unroll
    for (int r = 0; r < 4; r++) {
        int row = wm * 32 + (r >> 1) * 16 + (r & 1) * 8 + rg;
        xna[r] = sXNA[row]; tga[r] = sTGA[row];
    }
    float rpv[4], rnv[4]; int rpi[4], rni[4];
    #pragma unroll
    for (int r = 0; r < 4; r++) { rpv[r] = -FLT_MAX; rnv[r] = FLT_MAX; rpi[r] = NN; rni[r] = NN; }
    float cpv[16], cnv[16]; int cpi[16], cni[16];
    #pragma unroll
    for (int c = 0; c < 16; c++) { cpv[c] = -FLT_MAX; cnv[c] = FLT_MAX; cpi[c] = NN; cni[c] = NN; }

    #pragma unroll
    for (int ni = 0; ni < 8; ni++) {
        const int c0 = wn * 64 + ni * 8 + 2 * tq;
        const float xb0 = sXNB[c0], xb1 = sXNB[c0 + 1];
        const int tb0 = sTGB[c0], tb1 = sTGB[c0 + 1];
        const int j0 = jb + c0;
        #pragma unroll
        for (int mi = 0; mi < 2; mi++) {
            #pragma unroll
            for (int h = 0; h < 2; h++) {
                const int ri = mi * 2 + h;
                const int gi = ib + wm * 32 + mi * 16 + h * 8 + rg;  // global i
                const float d0 = acc[mi][ni][h * 2 + 0];
                const float d1 = acc[mi][ni][h * 2 + 1];
                // row side: candidate j for row i
                float s0 = fmaf(-2.0f, d0, xb0);
                float s1 = fmaf(-2.0f, d1, xb1);
                if (tb0 == tga[ri]) { if (s0 > rpv[ri]) { rpv[ri] = s0; rpi[ri] = j0; } }
                else                { if (s0 < rnv[ri]) { rnv[ri] = s0; rni[ri] = j0; } }
                if (tb1 == tga[ri]) { if (s1 > rpv[ri]) { rpv[ri] = s1; rpi[ri] = j0 + 1; } }
                else                { if (s1 < rnv[ri]) { rnv[ri] = s1; rni[ri] = j0 + 1; } }
                // col side: candidate i for row j (skip on diagonal)
                if (!diag) {
                    float t0 = fmaf(-2.0f, d0, xna[ri]);
                    float t1 = fmaf(-2.0f, d1, xna[ri]);
                    const int ci = ni * 2;
                    if (tb0 == tga[ri]) { if (t0 > cpv[ci]) { cpv[ci] = t0; cpi[ci] = gi; } }
                    else                 { if (t0 < cnv[ci]) { cnv[ci] = t0; cni[ci] = gi; } }
                    if (tb1 == tga[ri]) { if (t1 > cpv[ci + 1]) { cpv[ci + 1] = t1; cpi[ci + 1] = gi; } }
                    else                 { if (t1 < cnv[ci + 1]) { cnv[ci + 1] = t1; cni[ci + 1] = gi; } }
                }
            }
        }
    }

    // row-side merge across tq lanes (same rows, disjoint cols)
    #pragma unroll
    for (int r = 0; r < 4; r++) {
        #pragma unroll
        for (int off = 1; off <= 2; off <<= 1) {
            float ov = __shfl_xor_sync(0xffffffffu, rpv[r], off);
            int oi = __shfl_xor_sync(0xffffffffu, rpi[r], off);
            if (ov > rpv[r] || (ov == rpv[r] && oi < rpi[r])) { rpv[r] = ov; rpi[r] = oi; }
            ov = __shfl_xor_sync(0xffffffffu, rnv[r], off);
            oi = __shfl_xor_sync(0xffffffffu, rni[r], off);
            if (ov < rnv[r] || (ov == rnv[r] && oi < rni[r])) { rnv[r] = ov; rni[r] = oi; }
        }
    }
    // col-side merge across rg lanes (same cols, disjoint rows)
    if (!diag) {
        #pragma unroll
        for (int c = 0; c < 16; c++) {
            #pragma unroll
            for (int off = 4; off <= 16; off <<= 1) {
                float ov = __shfl_xor_sync(0xffffffffu, cpv[c], off);
                int oi = __shfl_xor_sync(0xffffffffu, cpi[c], off);
                if (ov > cpv[c] || (ov == cpv[c] && oi < cpi[c])) { cpv[c] = ov; cpi[c] = oi; }
                ov = __shfl_xor_sync(0xffffffffu, cnv[c], off);
                oi = __shfl_xor_sync(0xffffffffu, cni[c], off);
                if (ov < cnv[c] || (ov == cnv[c] && oi < cni[c])) { cnv[c] = ov; cni[c] = oi; }
            }
        }
    }

    float* mrpv = (float*)(sm + S_RPV); int* mrpi = (int*)(sm + S_RPI);
    float* mrnv = (float*)(sm + S_RNV); int* mrni = (int*)(sm + S_RNI);
    float* mcpv = (float*)(sm + S_CPV); int* mcpi = (int*)(sm + S_CPI);
    float* mcnv = (float*)(sm + S_CNV); int* mcni = (int*)(sm + S_CNI);

    if (tq == 0) {
        #pragma unroll
        for (int r = 0; r < 4; r++) {
            int row = wm * 32 + (r >> 1) * 16 + (r & 1) * 8 + rg;
            mrpv[wn * 128 + row] = rpv[r]; mrpi[wn * 128 + row] = rpi[r];
            mrnv[wn * 128 + row] = rnv[r]; mrni[wn * 128 + row] = rni[r];
        }
    }
    if (!diag && rg == 0) {
        #pragma unroll
        for (int c = 0; c < 16; c++) {
            int col = wn * 64 + (c >> 1) * 8 + 2 * tq + (c & 1);
            mcpv[wm * 128 + col] = cpv[c]; mcpi[wm * 128 + col] = cpi[c];
            mcnv[wm * 128 + col] = cnv[c]; mcni[wm * 128 + col] = cni[c];
        }
    }
    __syncthreads();

    if (tid < 128) {
        float pv = mrpv[tid]; int pi = mrpi[tid];
        float v = mrpv[128 + tid]; int id = mrpi[128 + tid];
        if (v > pv || (v == pv && id < pi)) { pv = v; pi = id; }
        float nv = mrnv[tid]; int nix = mrni[tid];
        v = mrnv[128 + tid]; id = mrni[128 + tid];
        if (v < nv || (v == nv && id < nix)) { nv = v; nix = id; }
        size_t o = (size_t)(ib + tid) * NB + bj;
        g_pv[o] = pv; g_pi[o] = pi; g_nv[o] = nv; g_ni[o] = nix;
    } else if (!diag) {
        int col = tid - 128;
        float pv = -FLT_MAX, nv = FLT_MAX;
        int pi = NN, nix = NN;
        #pragma unroll
        for (int w = 0; w < 4; w++) {
            float v = mcpv[w * 128 + col]; int id = mcpi[w * 128 + col];
            if (v > pv || (v == pv && id < pi)) { pv = v; pi = id; }
            v = mcnv[w * 128 + col]; id = mcni[w * 128 + col];
            if (v < nv || (v == nv && id < nix)) { nv = v; nix = id; }
        }
        size_t o = (size_t)(jb + col) * NB + bi;
        g_pv[o] = pv; g_pi[o] = pi; g_nv[o] = nv; g_ni[o] = nix;
    }
}

// ---------------- K3: merge 64 slots, gather triplets, partial sums ----------------
__global__ void terms_kernel(const float* __restrict__ x, const int* __restrict__ tg) {
    __shared__ float red[4 * 9];
    int tid = threadIdx.x;
    int lane = tid & 31, wrp = tid >> 5;
    int row = blockIdx.x * 128 + tid;

    float pv = -FLT_MAX, nv = FLT_MAX;
    int gp = NN, gn = NN;
    size_t base = (size_t)row * NB;
    #pragma unroll 8
    for (int s = 0; s < NB; s++) {
        float v = g_pv[base + s]; int id = g_pi[base + s];
        if (v > pv || (v == pv && id < gp)) { pv = v; gp = id; }
        v = g_nv[base + s]; id = g_ni[base + s];
        if (v < nv || (v == nv && id < gn)) { nv = v; gn = id; }
    }
    int t = tg[row];
    int cs = g_hist[t];
    float vf = (cs > 1 && (NN - cs) >= 1) ? 1.0f : 0.0f;
    gp = min(max(gp, 0), NN - 1);
    gn = min(max(gn, 0), NN - 1);
    int ppos = g_ps[t * NN + gp] - 1;
    int pneg = gn - g_ps[t * NN + gn];
    ppos = min(max(ppos, 0), NN - 1);
    pneg = min(max(pneg, 0), NN - 1);

    const float4* A = reinterpret_cast<const float4*>(x) + (size_t)row * 32;
    const float4* P = reinterpret_cast<const float4*>(x) + (size_t)ppos * 32;
    const float4* Q = reinterpret_cast<const float4*>(x) + (size_t)pneg * 32;
    float ap = 0, an = 0, npd = 0, l1a = 0, l1p = 0, l1n = 0;
    #pragma unroll
    for (int q = 0; q < 32; q++) {
        float4 a = A[q], p = P[q], n = Q[q];
        float d;
        d = a.x - p.x; ap = fmaf(d, d, ap);
        d = a.y - p.y; ap = fmaf(d, d, ap);
        d = a.z - p.z; ap = fmaf(d, d, ap);
        d = a.w - p.w; ap = fmaf(d, d, ap);
        d = a.x - n.x; an = fmaf(d, d, an);
        d = a.y - n.y; an = fmaf(d, d, an);
        d = a.z - n.z; an = fmaf(d, d, an);
        d = a.w - n.w; an = fmaf(d, d, an);
        d = p.x - n.x; npd = fmaf(d, d, npd);
        d = p.y - n.y; npd = fmaf(d, d, npd);
        d = p.z - n.z; npd = fmaf(d, d, npd);
        d = p.w - n.w; npd = fmaf(d, d, npd);
        l1a += fabsf(a.x) + fabsf(a.y) + fabsf(a.z) + fabsf(a.w);
        l1p += fabsf(p.x) + fabsf(p.y) + fabsf(p.z) + fabsf(p.w);
        l1n += fabsf(n.x) + fabsf(n.y) + fabsf(n.z) + fabsf(n.w);
    }
    float tl = fmaxf(ap - an + FMARGIN, 0.0f) * vf;

    float vals[9];
    vals[0] = tl;
    vals[1] = (tl > 0.0f) ? 1.0f : 0.0f;
    vals[2] = l1a * vf;
    vals[3] = l1p * vf;
    vals[4] = l1n * vf;
    vals[5] = ap * vf;
    vals[6] = an * vf;
    vals[7] = (ap - an - npd) * vf;
    vals[8] = vf;

    #pragma unroll
    for (int k = 0; k < 9; k++) {
        float v = vals[k];
        #pragma unroll
        for (int o = 16; o > 0; o >>= 1) v += __shfl_down_sync(0xffffffffu, v, o);
        if (lane == 0) red[wrp * 9 + k] = v;
    }
    __syncthreads();
    if (tid < 9)
        g_part[blockIdx.x * 9 + tid] = red[tid] + red[9 + tid] + red[18 + tid] + red[27 + tid];
}

// ---------------- K4: finalize ----------------
__global__ void final_kernel(float* __restrict__ out, int out_size) {
    __shared__ float r[6];
    if (threadIdx.x == 0) {
        float s[9];
        for (int k = 0; k < 9; k++) s[k] = 0.0f;
        for (int b = 0; b < 64; b++)
            for (int k = 0; k < 9; k++) s[k] += g_part[b * 9 + k];
        float vcount = s[8];
        float inv = (vcount > 0.0f) ? (1.0f / vcount) : 0.0f;
        float trip = (s[1] > 0.0f) ? (s[0] / s[1]) : (s[0] * inv);
        float sparse = (s[2] + s[3] + s[4]) * inv * (1.0f / 3.0f);
        float pw = s[7] * inv;
        if (pw < 0.0f) pw = 0.0f;
        r[0] = trip; r[1] = sparse; r[2] = pw;
        r[3] = vcount; r[4] = s[5] * inv; r[5] = s[6] * inv;
    }
    __syncthreads();
    for (int i = threadIdx.x; i < out_size; i += blockDim.x)
        out[i] = (i < 6) ? r[i] : 0.0f;
}

// ---------------- launch ----------------
extern "C" void kernel_launch(void* const* d_in, const int* in_sizes, int n_in,
                              void* d_out, int out_size) {
    const float* x = (const float*)d_in[0];
    const int* tg = (const int*)d_in[1];

    cudaFuncSetAttribute(dist_mma_kernel, cudaFuncAttributeMaxDynamicSharedMemorySize,
                         S_TOT);

    prep_kernel<<<64, 128>>>(x);
    prefix_kernel<<<CC, 256>>>(tg);
    dist_mma_kernel<<<NPAIRS, 256, S_TOT>>>(tg);
    terms_kernel<<<64, 128>>>(x, tg);
    final_kernel<<<1, 64>>>((float*)d_out, out_size);
}

// round 7
// speedup vs baseline: 2.6478x; 1.1808x over previous
#include <cuda_runtime.h>
#include <cuda_fp16.h>
#include <cfloat>
#include <cstdint>

#define NN 8192
#define DD 128
#define CC 64
#define FMARGIN 0.5f
#define NB 64
#define NCTAS 288          // sum over bi of ceil((64-bi)/8)

typedef unsigned long long u64;

// smem byte offsets
#define S_AHI 0            // 128 x 256B swizzled
#define S_ALO 32768
#define S_BHI 65536        // + buf*32768 (2 bufs)
#define S_BLO 131072       // + buf*32768 (2 bufs)
#define S_XNA 196608       // 128 f32
#define S_TGA 197120       // 128 i32
#define S_XNB 197632       // + buf*512
#define S_TGB 198656       // + buf*512
#define S_TOT 199680

// ---------------- device scratch ----------------
__device__ __half g_h16[NN * DD];
__device__ __half g_l16[NN * DD];
__device__ float g_xn[NN];
__device__ int   g_ps[CC * NN];
__device__ int   g_hist[CC];
__device__ u64   g_pkey[NN];
__device__ u64   g_nkey[NN];
__device__ float g_part[64 * 9];

// ---------------- PTX helpers ----------------
__device__ __forceinline__ uint32_t smem_u32(const void* p) {
    uint32_t a;
    asm("{ .reg .u64 t; cvta.to.shared.u64 t, %1; cvt.u32.u64 %0, t; }" : "=r"(a) : "l"(p));
    return a;
}
__device__ __forceinline__ uint64_t gbl_u64(const void* p) {
    uint64_t a;
    asm("cvta.to.global.u64 %0, %1;" : "=l"(a) : "l"(p));
    return a;
}
__device__ __forceinline__ void cpa16(uint32_t dst, uint64_t src) {
    asm volatile("cp.async.cg.shared.global [%0], [%1], 16;" :: "r"(dst), "l"(src));
}
__device__ __forceinline__ void cpa4(uint32_t dst, uint64_t src) {
    asm volatile("cp.async.ca.shared.global [%0], [%1], 4;" :: "r"(dst), "l"(src));
}
#define CPA_COMMIT() asm volatile("cp.async.commit_group;" ::: "memory")
#define CPA_WAIT0()  asm volatile("cp.async.wait_group 0;" ::: "memory")

__device__ __forceinline__ void ldsm4(uint32_t* r, uint32_t addr) {
    asm volatile("ldmatrix.sync.aligned.m8n8.x4.shared.b16 {%0,%1,%2,%3}, [%4];"
                 : "=r"(r[0]), "=r"(r[1]), "=r"(r[2]), "=r"(r[3]) : "r"(addr));
}
__device__ __forceinline__ void mma_f16(float* d, const uint32_t* a, uint32_t b0, uint32_t b1) {
    asm volatile(
        "mma.sync.aligned.m16n8k16.row.col.f32.f16.f16.f32 "
        "{%0,%1,%2,%3}, {%4,%5,%6,%7}, {%8,%9}, {%0,%1,%2,%3};"
        : "+f"(d[0]), "+f"(d[1]), "+f"(d[2]), "+f"(d[3])
        : "r"(a[0]), "r"(a[1]), "r"(a[2]), "r"(a[3]), "r"(b0), "r"(b1));
}
// order-preserving float->u32 encoding (monotone, no NaNs in data)
__device__ __forceinline__ uint32_t encf(float f) {
    uint32_t u = __float_as_uint(f);
    return (u & 0x80000000u) ? ~u : (u | 0x80000000u);
}

// ---------------- K-1: reset atomic key tables (required per graph replay) ----------------
__global__ void init_keys() {
    int i = blockIdx.x * 256 + threadIdx.x;
    g_pkey[i] = 0ull;
    g_nkey[i] = ~0ull;
}

// ---------------- K0: fp16 split + norms ----------------
__global__ void prep_kernel(const float* __restrict__ x) {
    int row = blockIdx.x * blockDim.x + threadIdx.x;
    const float4* xr = reinterpret_cast<const float4*>(x) + (size_t)row * 32;
    __half2* hr = reinterpret_cast<__half2*>(g_h16) + (size_t)row * 64;
    __half2* lr = reinterpret_cast<__half2*>(g_l16) + (size_t)row * 64;
    float s = 0.0f;
    #pragma unroll
    for (int q = 0; q < 32; q++) {
        float4 v = xr[q];
        __half hx = __float2half_rn(v.x), hy = __float2half_rn(v.y);
        __half hz = __float2half_rn(v.z), hw = __float2half_rn(v.w);
        float lx = v.x - __half2float(hx), ly = v.y - __half2float(hy);
        float lz = v.z - __half2float(hz), lw = v.w - __half2float(hw);
        hr[2 * q + 0] = __halves2half2(hx, hy);
        hr[2 * q + 1] = __halves2half2(hz, hw);
        lr[2 * q + 0] = __halves2half2(__float2half_rn(lx), __float2half_rn(ly));
        lr[2 * q + 1] = __halves2half2(__float2half_rn(lz), __float2half_rn(lw));
        s = fmaf(v.x, v.x, s); s = fmaf(v.y, v.y, s);
        s = fmaf(v.z, v.z, s); s = fmaf(v.w, v.w, s);
    }
    g_xn[row] = s;
}

// ---------------- K1: per-class inclusive prefix counts ----------------
__global__ void prefix_kernel(const int* __restrict__ tg) {
    int c = blockIdx.x;
    __shared__ int wsum[8];
    __shared__ int wpre[8];
    __shared__ int stot;
    int lane = threadIdx.x & 31, wid = threadIdx.x >> 5;
    int run = 0;
    for (int base = 0; base < NN; base += 256) {
        int f = (tg[base + threadIdx.x] == c) ? 1 : 0;
        int s = f;
        #pragma unroll
        for (int o = 1; o < 32; o <<= 1) {
            int v = __shfl_up_sync(0xffffffffu, s, o);
            if (lane >= o) s += v;
        }
        if (lane == 31) wsum[wid] = s;
        __syncthreads();
        if (threadIdx.x == 0) {
            int a = 0;
            for (int w = 0; w < 8; w++) { wpre[w] = a; a += wsum[w]; }
            stot = a;
        }
        __syncthreads();
        g_ps[c * NN + base + threadIdx.x] = run + wpre[wid] + s;
        run += stot;
        __syncthreads();
    }
    if (threadIdx.x == 0) g_hist[c] = run;
}

// load a 128-row fp16 block (hi+lo) into swizzled smem via cp.async
__device__ __forceinline__ void load_blk(uint64_t GH, uint64_t GL,
                                         uint32_t dhi, uint32_t dlo,
                                         int rowbase, int tid) {
    #pragma unroll
    for (int u = 0; u < 8; u++) {
        int idx = tid + u * 256;                   // 0..2047
        int r = idx >> 4, kc = idx & 15;
        uint64_t off = (((size_t)(rowbase + r) * DD + kc * 8) << 1);
        uint32_t so = r * 256 + (((uint32_t)kc ^ (r & 7)) << 4);
        cpa16(dhi + so, GH + off);
        cpa16(dlo + so, GL + off);
    }
}

// ---------------- K2: triangular streamed fp16-split mma ----------------
// CTA = (block-row bi, chunk of <=8 bj tiles). A persistent, B double-buffered.
__global__ void __launch_bounds__(256, 1)
dist_mma_kernel(const int* __restrict__ tg) {
    extern __shared__ char sm[];
    const uint32_t sb = smem_u32(sm);
    const uint64_t GH = gbl_u64(g_h16);
    const uint64_t GL = gbl_u64(g_l16);
    const uint64_t GX = gbl_u64(g_xn);
    const uint64_t GT = gbl_u64(tg);

    // decode blockIdx.x -> (bi, chunk)
    int bi = 0, rem = blockIdx.x, ch;
    while (rem >= (ch = ((NB - bi + 7) >> 3))) { rem -= ch; bi++; }
    const int jblk0 = bi + rem * 8;
    const int jc = min(8, NB - jblk0);
    const int ib = bi * 128;

    const int tid = threadIdx.x;
    const int lane = tid & 31;
    const int wid = tid >> 5;
    const int wm = wid >> 1;
    const int wn = wid & 1;
    const int tq = lane & 3;
    const int rg = lane >> 2;
    const uint32_t x7 = lane & 7;
    const uint32_t ahit = lane >> 4;
    const uint32_t bhit = (lane >> 3) & 1;
    const uint32_t arow0 = wm * 32 + (lane & 15);
    const uint32_t arow1 = arow0 + 16;

    // initial loads: A(hi+lo) + metaA + B(tile0) + metaB0
    load_blk(GH, GL, sb + S_AHI, sb + S_ALO, ib, tid);
    if (tid < 128) cpa4(sb + S_XNA + tid * 4, GX + ((size_t)(ib + tid) << 2));
    else           cpa4(sb + S_TGA + (tid - 128) * 4, GT + ((size_t)(ib + tid - 128) << 2));
    load_blk(GH, GL, sb + S_BHI, sb + S_BLO, jblk0 * 128, tid);
    if (tid < 128) cpa4(sb + S_XNB + tid * 4, GX + ((size_t)(jblk0 * 128 + tid) << 2));
    else           cpa4(sb + S_TGB + (tid - 128) * 4, GT + ((size_t)(jblk0 * 128 + tid - 128) << 2));
    CPA_COMMIT();
    CPA_WAIT0();
    __syncthreads();

    float xna[4]; int tga[4];
    #pragma unroll
    for (int r = 0; r < 4; r++) {
        int row = wm * 32 + (r >> 1) * 16 + (r & 1) * 8 + rg;
        xna[r] = *reinterpret_cast<const float*>(sm + S_XNA + row * 4);
        tga[r] = *reinterpret_cast<const int*>(sm + S_TGA + row * 4);
    }
    float rpv[4], rnv[4]; int rpi[4], rni[4];
    #pragma unroll
    for (int r = 0; r < 4; r++) { rpv[r] = -FLT_MAX; rnv[r] = FLT_MAX; rpi[r] = NN; rni[r] = NN; }

    for (int t = 0; t < jc; t++) {
        const int buf = t & 1;
        const int bj = jblk0 + t;
        const int jb = bj * 128;

        // prefetch next B tile + meta into the other buffer
        if (t + 1 < jc) {
            const int nb2 = (t + 1) & 1;
            load_blk(GH, GL, sb + S_BHI + nb2 * 32768, sb + S_BLO + nb2 * 32768,
                     (bj + 1) * 128, tid);
            if (tid < 128) cpa4(sb + S_XNB + nb2 * 512 + tid * 4,
                                GX + ((size_t)((bj + 1) * 128 + tid) << 2));
            else           cpa4(sb + S_TGB + nb2 * 512 + (tid - 128) * 4,
                                GT + ((size_t)((bj + 1) * 128 + tid - 128) << 2));
            CPA_COMMIT();
        }

        // ---- compute 128x128 tile, 3 fused fp16-split passes ----
        float acc[2][8][4];
        #pragma unroll
        for (int mi = 0; mi < 2; mi++)
            #pragma unroll
            for (int ni = 0; ni < 8; ni++)
                #pragma unroll
                for (int c = 0; c < 4; c++) acc[mi][ni][c] = 0.0f;

        const uint32_t bhb = sb + S_BHI + buf * 32768;
        const uint32_t blb = sb + S_BLO + buf * 32768;
        #pragma unroll
        for (int ks = 0; ks < 8; ks++) {
            uint32_t ah[2][4], al[2][4], bh[4][4], bl[4][4];
            const uint32_t swzA = (((uint32_t)(2 * ks) + ahit) ^ x7) << 4;
            const uint32_t swzB = (((uint32_t)(2 * ks) + bhit) ^ x7) << 4;
            ldsm4(ah[0], sb + S_AHI + arow0 * 256 + swzA);
            ldsm4(ah[1], sb + S_AHI + arow1 * 256 + swzA);
            ldsm4(al[0], sb + S_ALO + arow0 * 256 + swzA);
            ldsm4(al[1], sb + S_ALO + arow1 * 256 + swzA);
            #pragma unroll
            for (int q = 0; q < 4; q++) {
                uint32_t brow = wn * 64 + q * 16 + x7 + (ahit << 3);
                ldsm4(bh[q], bhb + brow * 256 + swzB);
                ldsm4(bl[q], blb + brow * 256 + swzB);
            }
            #pragma unroll
            for (int mi = 0; mi < 2; mi++) {
                #pragma unroll
                for (int ni = 0; ni < 8; ni++) {
                    const int q = ni >> 1, p = (ni & 1) * 2;
                    mma_f16(acc[mi][ni], ah[mi], bh[q][p], bh[q][p + 1]);
                    mma_f16(acc[mi][ni], ah[mi], bl[q][p], bl[q][p + 1]);
                    mma_f16(acc[mi][ni], al[mi], bh[q][p], bh[q][p + 1]);
                }
            }
        }

        // ---- epilogue ----
        const float* sxb = reinterpret_cast<const float*>(sm + S_XNB + buf * 512);
        const int*   stb = reinterpret_cast<const int*>(sm + S_TGB + buf * 512);
        const bool offd = (bj > bi);

        #pragma unroll
        for (int ni = 0; ni < 8; ni++) {
            const int c0 = wn * 64 + ni * 8 + 2 * tq;
            const float xb0 = sxb[c0], xb1 = sxb[c0 + 1];
            const int tb0 = stb[c0], tb1 = stb[c0 + 1];
            const int j0 = jb + c0;
            u64 pk0 = 0ull, pk1 = 0ull, nk0 = ~0ull, nk1 = ~0ull;
            #pragma unroll
            for (int mi = 0; mi < 2; mi++) {
                #pragma unroll
                for (int h = 0; h < 2; h++) {
                    const int ri = mi * 2 + h;
                    const int gi = ib + wm * 32 + mi * 16 + h * 8 + rg;
                    const float d0 = acc[mi][ni][h * 2 + 0];
                    const float d1 = acc[mi][ni][h * 2 + 1];
                    // row side: candidate j for row i
                    float s0 = fmaf(-2.0f, d0, xb0);
                    float s1 = fmaf(-2.0f, d1, xb1);
                    if (tb0 == tga[ri]) { if (s0 > rpv[ri]) { rpv[ri] = s0; rpi[ri] = j0; } }
                    else                { if (s0 < rnv[ri]) { rnv[ri] = s0; rni[ri] = j0; } }
                    if (tb1 == tga[ri]) { if (s1 > rpv[ri]) { rpv[ri] = s1; rpi[ri] = j0 + 1; } }
                    else                { if (s1 < rnv[ri]) { rnv[ri] = s1; rni[ri] = j0 + 1; } }
                    // col side: candidate i for row j (skip on diagonal tile)
                    if (offd) {
                        float t0 = fmaf(-2.0f, d0, xna[ri]);
                        float t1 = fmaf(-2.0f, d1, xna[ri]);
                        if (tb0 == tga[ri]) {
                            u64 k = ((u64)encf(t0) << 32) | (uint32_t)(~(uint32_t)gi);
                            if (k > pk0) pk0 = k;
                        } else {
                            u64 k = ((u64)encf(t0) << 32) | (uint32_t)gi;
                            if (k < nk0) nk0 = k;
                        }
                        if (tb1 == tga[ri]) {
                            u64 k = ((u64)encf(t1) << 32) | (uint32_t)(~(uint32_t)gi);
                            if (k > pk1) pk1 = k;
                        } else {
                            u64 k = ((u64)encf(t1) << 32) | (uint32_t)gi;
                            if (k < nk1) nk1 = k;
                        }
                    }
                }
            }
            if (offd) {
                #pragma unroll
                for (int off = 4; off <= 16; off <<= 1) {
                    u64 o;
                    o = __shfl_xor_sync(0xffffffffu, pk0, off); if (o > pk0) pk0 = o;
                    o = __shfl_xor_sync(0xffffffffu, pk1, off); if (o > pk1) pk1 = o;
                    o = __shfl_xor_sync(0xffffffffu, nk0, off); if (o < nk0) nk0 = o;
                    o = __shfl_xor_sync(0xffffffffu, nk1, off); if (o < nk1) nk1 = o;
                }
                if (rg == 0) {
                    atomicMax(&g_pkey[j0], pk0);
                    atomicMax(&g_pkey[j0 + 1], pk1);
                    atomicMin(&g_nkey[j0], nk0);
                    atomicMin(&g_nkey[j0 + 1], nk1);
                }
            }
        }

        CPA_WAIT0();
        __syncthreads();
    }

    // ---- flush row-side running state ----
    #pragma unroll
    for (int r = 0; r < 4; r++) {
        float pv = rpv[r]; int pi2 = rpi[r];
        float nv = rnv[r]; int ni2 = rni[r];
        #pragma unroll
        for (int off = 1; off <= 2; off <<= 1) {
            float ov = __shfl_xor_sync(0xffffffffu, pv, off);
            int oi = __shfl_xor_sync(0xffffffffu, pi2, off);
            if (ov > pv || (ov == pv && oi < pi2)) { pv = ov; pi2 = oi; }
            ov = __shfl_xor_sync(0xffffffffu, nv, off);
            oi = __shfl_xor_sync(0xffffffffu, ni2, off);
            if (ov < nv || (ov == nv && oi < ni2)) { nv = ov; ni2 = oi; }
        }
        if (tq == 0) {
            int row = ib + wm * 32 + (r >> 1) * 16 + (r & 1) * 8 + rg;
            atomicMax(&g_pkey[row], ((u64)encf(pv) << 32) | (uint32_t)(~(uint32_t)pi2));
            atomicMin(&g_nkey[row], ((u64)encf(nv) << 32) | (uint32_t)ni2);
        }
    }
}

// ---------------- K3: decode keys, gather triplets, partial sums ----------------
__global__ void terms_kernel(const float* __restrict__ x, const int* __restrict__ tg) {
    __shared__ float red[4 * 9];
    int tid = threadIdx.x;
    int lane = tid & 31, wrp = tid >> 5;
    int row = blockIdx.x * 128 + tid;

    u64 pk = g_pkey[row], nk = g_nkey[row];
    int gp = (int)(~(uint32_t)pk);
    int gn = (int)((uint32_t)nk);

    int t = tg[row];
    int cs = g_hist[t];
    float vf = (cs > 1 && (NN - cs) >= 1) ? 1.0f : 0.0f;
    gp = min(max(gp, 0), NN - 1);
    gn = min(max(gn, 0), NN - 1);
    int ppos = g_ps[t * NN + gp] - 1;
    int pneg = gn - g_ps[t * NN + gn];
    ppos = min(max(ppos, 0), NN - 1);
    pneg = min(max(pneg, 0), NN - 1);

    const float4* A = reinterpret_cast<const float4*>(x) + (size_t)row * 32;
    const float4* P = reinterpret_cast<const float4*>(x) + (size_t)ppos * 32;
    const float4* Q = reinterpret_cast<const float4*>(x) + (size_t)pneg * 32;
    float ap = 0, an = 0, npd = 0, l1a = 0, l1p = 0, l1n = 0;
    #pragma unroll
    for (int q = 0; q < 32; q++) {
        float4 a = A[q], p = P[q], n = Q[q];
        float d;
        d = a.x - p.x; ap = fmaf(d, d, ap);
        d = a.y - p.y; ap = fmaf(d, d, ap);
        d = a.z - p.z; ap = fmaf(d, d, ap);
        d = a.w - p.w; ap = fmaf(d, d, ap);
        d = a.x - n.x; an = fmaf(d, d, an);
        d = a.y - n.y; an = fmaf(d, d, an);
        d = a.z - n.z; an = fmaf(d, d, an);
        d = a.w - n.w; an = fmaf(d, d, an);
        d = p.x - n.x; npd = fmaf(d, d, npd);
        d = p.y - n.y; npd = fmaf(d, d, npd);
        d = p.z - n.z; npd = fmaf(d, d, npd);
        d = p.w - n.w; npd = fmaf(d, d, npd);
        l1a += fabsf(a.x) + fabsf(a.y) + fabsf(a.z) + fabsf(a.w);
        l1p += fabsf(p.x) + fabsf(p.y) + fabsf(p.z) + fabsf(p.w);
        l1n += fabsf(n.x) + fabsf(n.y) + fabsf(n.z) + fabsf(n.w);
    }
    float tl = fmaxf(ap - an + FMARGIN, 0.0f) * vf;

    float vals[9];
    vals[0] = tl;
    vals[1] = (tl > 0.0f) ? 1.0f : 0.0f;
    vals[2] = l1a * vf;
    vals[3] = l1p * vf;
    vals[4] = l1n * vf;
    vals[5] = ap * vf;
    vals[6] = an * vf;
    vals[7] = (ap - an - npd) * vf;
    vals[8] = vf;

    #pragma unroll
    for (int k = 0; k < 9; k++) {
        float v = vals[k];
        #pragma unroll
        for (int o = 16; o > 0; o >>= 1) v += __shfl_down_sync(0xffffffffu, v, o);
        if (lane == 0) red[wrp * 9 + k] = v;
    }
    __syncthreads();
    if (tid < 9)
        g_part[blockIdx.x * 9 + tid] = red[tid] + red[9 + tid] + red[18 + tid] + red[27 + tid];
}

// ---------------- K4: finalize ----------------
__global__ void final_kernel(float* __restrict__ out, int out_size) {
    __shared__ float r[6];
    if (threadIdx.x == 0) {
        float s[9];
        for (int k = 0; k < 9; k++) s[k] = 0.0f;
        for (int b = 0; b < 64; b++)
            for (int k = 0; k < 9; k++) s[k] += g_part[b * 9 + k];
        float vcount = s[8];
        float inv = (vcount > 0.0f) ? (1.0f / vcount) : 0.0f;
        float trip = (s[1] > 0.0f) ? (s[0] / s[1]) : (s[0] * inv);
        float sparse = (s[2] + s[3] + s[4]) * inv * (1.0f / 3.0f);
        float pw = s[7] * inv;
        if (pw < 0.0f) pw = 0.0f;
        r[0] = trip; r[1] = sparse; r[2] = pw;
        r[3] = vcount; r[4] = s[5] * inv; r[5] = s[6] * inv;
    }
    __syncthreads();
    for (int i = threadIdx.x; i < out_size; i += blockDim.x)
        out[i] = (i < 6) ? r[i] : 0.0f;
}

// ---------------- launch ----------------
extern "C" void kernel_launch(void* const* d_in, const int* in_sizes, int n_in,
                              void* d_out, int out_size) {
    const float* x = (const float*)d_in[0];
    const int* tg = (const int*)d_in[1];

    cudaFuncSetAttribute(dist_mma_kernel, cudaFuncAttributeMaxDynamicSharedMemorySize,
                         S_TOT);

    init_keys<<<NN / 256, 256>>>();
    prep_kernel<<<64, 128>>>(x);
    prefix_kernel<<<CC, 256>>>(tg);
    dist_mma_kernel<<<NCTAS, 256, S_TOT>>>(tg);
    terms_kernel<<<64, 128>>>(x, tg);
    final_kernel<<<1, 64>>>((float*)d_out, out_size);
}

// round 9
// speedup vs baseline: 3.2550x; 1.2293x over previous
#include <cuda_runtime.h>
#include <cuda_fp16.h>
#include <cfloat>
#include <cstdint>

#define NN 8192
#define DD 128
#define CC 64
#define FMARGIN 0.5f
#define NB 64
#define NCTAS 288          // sum over bi of ceil((64-bi)/8)
#define NTHREADS 512

typedef unsigned long long u64;

// smem byte offsets
#define S_AHI 0            // 128 x 256B swizzled
#define S_ALO 32768
#define S_BHI 65536        // + buf*32768 (2 bufs)
#define S_BLO 131072       // + buf*32768 (2 bufs)
#define S_XNA 196608       // 128 f32
#define S_TGA 197120       // 128 i32
#define S_XNB 197632       // + buf*512
#define S_TGB 198656       // + buf*512
#define S_TOT 199680

// ---------------- device scratch ----------------
__device__ __half g_h16[NN * DD];
__device__ __half g_l16[NN * DD];
__device__ float g_xn[NN];
__device__ int   g_ps[CC * NN];
__device__ int   g_hist[CC];
__device__ u64   g_pkey[NN];
__device__ u64   g_nkey[NN];
__device__ float g_part[64 * 9];

// ---------------- PTX helpers ----------------
__device__ __forceinline__ uint32_t smem_u32(const void* p) {
    uint32_t a;
    asm("{ .reg .u64 t; cvta.to.shared.u64 t, %1; cvt.u32.u64 %0, t; }" : "=r"(a) : "l"(p));
    return a;
}
__device__ __forceinline__ uint64_t gbl_u64(const void* p) {
    uint64_t a;
    asm("cvta.to.global.u64 %0, %1;" : "=l"(a) : "l"(p));
    return a;
}
__device__ __forceinline__ void cpa16(uint32_t dst, uint64_t src) {
    asm volatile("cp.async.cg.shared.global [%0], [%1], 16;" :: "r"(dst), "l"(src));
}
__device__ __forceinline__ void cpa4(uint32_t dst, uint64_t src) {
    asm volatile("cp.async.ca.shared.global [%0], [%1], 4;" :: "r"(dst), "l"(src));
}
#define CPA_COMMIT() asm volatile("cp.async.commit_group;" ::: "memory")
#define CPA_WAIT0()  asm volatile("cp.async.wait_group 0;" ::: "memory")

__device__ __forceinline__ void ldsm4(uint32_t* r, uint32_t addr) {
    asm volatile("ldmatrix.sync.aligned.m8n8.x4.shared.b16 {%0,%1,%2,%3}, [%4];"
                 : "=r"(r[0]), "=r"(r[1]), "=r"(r[2]), "=r"(r[3]) : "r"(addr));
}
__device__ __forceinline__ void mma_f16(float* d, const uint32_t* a, uint32_t b0, uint32_t b1) {
    asm volatile(
        "mma.sync.aligned.m16n8k16.row.col.f32.f16.f16.f32 "
        "{%0,%1,%2,%3}, {%4,%5,%6,%7}, {%8,%9}, {%0,%1,%2,%3};"
        : "+f"(d[0]), "+f"(d[1]), "+f"(d[2]), "+f"(d[3])
        : "r"(a[0]), "r"(a[1]), "r"(a[2]), "r"(a[3]), "r"(b0), "r"(b1));
}
// order-preserving float->u32 encoding (monotone, no NaNs in data)
__device__ __forceinline__ uint32_t encf(float f) {
    uint32_t u = __float_as_uint(f);
    return (u & 0x80000000u) ? ~u : (u | 0x80000000u);
}

// ---------------- K-1: reset atomic key tables ----------------
__global__ void init_keys() {
    int i = blockIdx.x * 256 + threadIdx.x;
    g_pkey[i] = 0ull;
    g_nkey[i] = ~0ull;
}

// ---------------- K0: fp16 split + norms ----------------
__global__ void prep_kernel(const float* __restrict__ x) {
    int row = blockIdx.x * blockDim.x + threadIdx.x;
    const float4* xr = reinterpret_cast<const float4*>(x) + (size_t)row * 32;
    __half2* hr = reinterpret_cast<__half2*>(g_h16) + (size_t)row * 64;
    __half2* lr = reinterpret_cast<__half2*>(g_l16) + (size_t)row * 64;
    float s = 0.0f;
    #pragma unroll
    for (int q = 0; q < 32; q++) {
        float4 v = xr[q];
        __half hx = __float2half_rn(v.x), hy = __float2half_rn(v.y);
        __half hz = __float2half_rn(v.z), hw = __float2half_rn(v.w);
        float lx = v.x - __half2float(hx), ly = v.y - __half2float(hy);
        float lz = v.z - __half2float(hz), lw = v.w - __half2float(hw);
        hr[2 * q + 0] = __halves2half2(hx, hy);
        hr[2 * q + 1] = __halves2half2(hz, hw);
        lr[2 * q + 0] = __halves2half2(__float2half_rn(lx), __float2half_rn(ly));
        lr[2 * q + 1] = __halves2half2(__float2half_rn(lz), __float2half_rn(lw));
        s = fmaf(v.x, v.x, s); s = fmaf(v.y, v.y, s);
        s = fmaf(v.z, v.z, s); s = fmaf(v.w, v.w, s);
    }
    g_xn[row] = s;
}

// ---------------- K1: per-class inclusive prefix counts ----------------
__global__ void prefix_kernel(const int* __restrict__ tg) {
    int c = blockIdx.x;
    __shared__ int wsum[8];
    __shared__ int wpre[8];
    __shared__ int stot;
    int lane = threadIdx.x & 31, wid = threadIdx.x >> 5;
    int run = 0;
    for (int base = 0; base < NN; base += 256) {
        int f = (tg[base + threadIdx.x] == c) ? 1 : 0;
        int s = f;
        #pragma unroll
        for (int o = 1; o < 32; o <<= 1) {
            int v = __shfl_up_sync(0xffffffffu, s, o);
            if (lane >= o) s += v;
        }
        if (lane == 31) wsum[wid] = s;
        __syncthreads();
        if (threadIdx.x == 0) {
            int a = 0;
            for (int w = 0; w < 8; w++) { wpre[w] = a; a += wsum[w]; }
            stot = a;
        }
        __syncthreads();
        g_ps[c * NN + base + threadIdx.x] = run + wpre[wid] + s;
        run += stot;
        __syncthreads();
    }
    if (threadIdx.x == 0) g_hist[c] = run;
}

// load a 128-row fp16 block (hi+lo) into swizzled smem via cp.async (512 thr)
__device__ __forceinline__ void load_blk(uint64_t GH, uint64_t GL,
                                         uint32_t dhi, uint32_t dlo,
                                         int rowbase, int tid) {
    #pragma unroll
    for (int u = 0; u < 4; u++) {
        int idx = tid + u * NTHREADS;              // 0..2047
        int r = idx >> 4, kc = idx & 15;
        uint64_t off = (((size_t)(rowbase + r) * DD + kc * 8) << 1);
        uint32_t so = r * 256 + (((uint32_t)kc ^ (r & 7)) << 4);
        cpa16(dhi + so, GH + off);
        cpa16(dlo + so, GL + off);
    }
}

// ---------------- K2: triangular streamed fp16-split mma, 16 warps ----------------
__global__ void __launch_bounds__(NTHREADS, 1)
dist_mma_kernel(const int* __restrict__ tg) {
    extern __shared__ char sm[];
    const uint32_t sb = smem_u32(sm);
    const uint64_t GH = gbl_u64(g_h16);
    const uint64_t GL = gbl_u64(g_l16);
    const uint64_t GX = gbl_u64(g_xn);
    const uint64_t GT = gbl_u64(tg);

    // decode blockIdx.x -> (bi, chunk)
    int bi = 0, rem = blockIdx.x, ch;
    while (rem >= (ch = ((NB - bi + 7) >> 3))) { rem -= ch; bi++; }
    const int jblk0 = bi + rem * 8;
    const int jc = min(8, NB - jblk0);
    const int ib = bi * 128;

    const int tid = threadIdx.x;
    const int lane = tid & 31;
    const int wid = tid >> 5;            // 0..15
    const int wm = wid >> 2;             // 0..3 row group (32 rows)
    const int wn = wid & 3;              // 0..3 col group (32 cols)
    const int tq = lane & 3;
    const int rg = lane >> 2;
    const uint32_t x7 = lane & 7;
    const uint32_t ahit = lane >> 4;              // row-half select for ldmatrix
    const uint32_t bhit = (lane >> 3) & 1;        // k-chunk select for B ldmatrix
    const uint32_t arow0 = wm * 32 + (lane & 15);
    const uint32_t arow1 = arow0 + 16;

    // initial loads: A(hi+lo) + metaA + B(tile0) + metaB0
    load_blk(GH, GL, sb + S_AHI, sb + S_ALO, ib, tid);
    if (tid < 128)      cpa4(sb + S_XNA + tid * 4, GX + ((size_t)(ib + tid) << 2));
    else if (tid < 256) cpa4(sb + S_TGA + (tid - 128) * 4, GT + ((size_t)(ib + tid - 128) << 2));
    load_blk(GH, GL, sb + S_BHI, sb + S_BLO, jblk0 * 128, tid);
    if (tid < 128)      cpa4(sb + S_XNB + tid * 4, GX + ((size_t)(jblk0 * 128 + tid) << 2));
    else if (tid < 256) cpa4(sb + S_TGB + (tid - 128) * 4, GT + ((size_t)(jblk0 * 128 + tid - 128) << 2));
    CPA_COMMIT();
    CPA_WAIT0();
    __syncthreads();

    float xna[4]; int tga[4];
    #pragma unroll
    for (int r = 0; r < 4; r++) {
        int row = wm * 32 + (r >> 1) * 16 + (r & 1) * 8 + rg;
        xna[r] = *reinterpret_cast<const float*>(sm + S_XNA + row * 4);
        tga[r] = *reinterpret_cast<const int*>(sm + S_TGA + row * 4);
    }
    float rpv[4], rnv[4]; int rpi[4], rni[4];
    #pragma unroll
    for (int r = 0; r < 4; r++) { rpv[r] = -FLT_MAX; rnv[r] = FLT_MAX; rpi[r] = NN; rni[r] = NN; }

    for (int t = 0; t < jc; t++) {
        const int buf = t & 1;
        const int bj = jblk0 + t;
        const int jb = bj * 128;

        // prefetch next B tile + meta into the other buffer
        if (t + 1 < jc) {
            const int nb2 = (t + 1) & 1;
            load_blk(GH, GL, sb + S_BHI + nb2 * 32768, sb + S_BLO + nb2 * 32768,
                     (bj + 1) * 128, tid);
            if (tid < 128)      cpa4(sb + S_XNB + nb2 * 512 + tid * 4,
                                     GX + ((size_t)((bj + 1) * 128 + tid) << 2));
            else if (tid < 256) cpa4(sb + S_TGB + nb2 * 512 + (tid - 128) * 4,
                                     GT + ((size_t)((bj + 1) * 128 + tid - 128) << 2));
            CPA_COMMIT();
        }

        // ---- compute 128x128 tile: warp tile 32x32, 3 pass-separated loops ----
        float acc[2][4][4];
        #pragma unroll
        for (int mi = 0; mi < 2; mi++)
            #pragma unroll
            for (int ni = 0; ni < 4; ni++)
                #pragma unroll
                for (int c = 0; c < 4; c++) acc[mi][ni][c] = 0.0f;

        const uint32_t bhb = sb + S_BHI + buf * 32768;
        const uint32_t blb = sb + S_BLO + buf * 32768;
        #pragma unroll
        for (int ks = 0; ks < 8; ks++) {
            uint32_t ah[2][4], al[2][4], bh[2][4], bl[2][4];
            const uint32_t swzA = (((uint32_t)(2 * ks) + ahit) ^ x7) << 4;
            const uint32_t swzB = (((uint32_t)(2 * ks) + bhit) ^ x7) << 4;
            ldsm4(ah[0], sb + S_AHI + arow0 * 256 + swzA);
            ldsm4(ah[1], sb + S_AHI + arow1 * 256 + swzA);
            ldsm4(al[0], sb + S_ALO + arow0 * 256 + swzA);
            ldsm4(al[1], sb + S_ALO + arow1 * 256 + swzA);
            #pragma unroll
            for (int q = 0; q < 2; q++) {
                uint32_t brow = wn * 32 + q * 16 + x7 + (ahit << 3);
                ldsm4(bh[q], bhb + brow * 256 + swzB);
                ldsm4(bl[q], blb + brow * 256 + swzB);
            }
            // pass 1: hi*hi — 8 independent MMAs
            #pragma unroll
            for (int mi = 0; mi < 2; mi++)
                #pragma unroll
                for (int ni = 0; ni < 4; ni++) {
                    const int q = ni >> 1, p = (ni & 1) * 2;
                    mma_f16(acc[mi][ni], ah[mi], bh[q][p], bh[q][p + 1]);
                }
            // pass 2: hi*lo
            #pragma unroll
            for (int mi = 0; mi < 2; mi++)
                #pragma unroll
                for (int ni = 0; ni < 4; ni++) {
                    const int q = ni >> 1, p = (ni & 1) * 2;
                    mma_f16(acc[mi][ni], ah[mi], bl[q][p], bl[q][p + 1]);
                }
            // pass 3: lo*hi
            #pragma unroll
            for (int mi = 0; mi < 2; mi++)
                #pragma unroll
                for (int ni = 0; ni < 4; ni++) {
                    const int q = ni >> 1, p = (ni & 1) * 2;
                    mma_f16(acc[mi][ni], al[mi], bh[q][p], bh[q][p + 1]);
                }
        }

        // ---- epilogue ----
        const float* sxb = reinterpret_cast<const float*>(sm + S_XNB + buf * 512);
        const int*   stb = reinterpret_cast<const int*>(sm + S_TGB + buf * 512);
        const bool offd = (bj > bi);

        #pragma unroll
        for (int ni = 0; ni < 4; ni++) {
            const int c0 = wn * 32 + ni * 8 + 2 * tq;
            const float xb0 = sxb[c0], xb1 = sxb[c0 + 1];
            const int tb0 = stb[c0], tb1 = stb[c0 + 1];
            const int j0 = jb + c0;
            u64 pk0 = 0ull, pk1 = 0ull, nk0 = ~0ull, nk1 = ~0ull;
            #pragma unroll
            for (int mi = 0; mi < 2; mi++) {
                #pragma unroll
                for (int h = 0; h < 2; h++) {
                    const int ri = mi * 2 + h;
                    const int gi = ib + wm * 32 + mi * 16 + h * 8 + rg;
                    const float d0 = acc[mi][ni][h * 2 + 0];
                    const float d1 = acc[mi][ni][h * 2 + 1];
                    float s0 = fmaf(-2.0f, d0, xb0);
                    float s1 = fmaf(-2.0f, d1, xb1);
                    if (tb0 == tga[ri]) { if (s0 > rpv[ri]) { rpv[ri] = s0; rpi[ri] = j0; } }
                    else                { if (s0 < rnv[ri]) { rnv[ri] = s0; rni[ri] = j0; } }
                    if (tb1 == tga[ri]) { if (s1 > rpv[ri]) { rpv[ri] = s1; rpi[ri] = j0 + 1; } }
                    else                { if (s1 < rnv[ri]) { rnv[ri] = s1; rni[ri] = j0 + 1; } }
                    if (offd) {
                        float t0 = fmaf(-2.0f, d0, xna[ri]);
                        float t1 = fmaf(-2.0f, d1, xna[ri]);
                        if (tb0 == tga[ri]) {
                            u64 k = ((u64)encf(t0) << 32) | (uint32_t)(~(uint32_t)gi);
                            if (k > pk0) pk0 = k;
                        } else {
                            u64 k = ((u64)encf(t0) << 32) | (uint32_t)gi;
                            if (k < nk0) nk0 = k;
                        }
                        if (tb1 == tga[ri]) {
                            u64 k = ((u64)encf(t1) << 32) | (uint32_t)(~(uint32_t)gi);
                            if (k > pk1) pk1 = k;
                        } else {
                            u64 k = ((u64)encf(t1) << 32) | (uint32_t)gi;
                            if (k < nk1) nk1 = k;
                        }
                    }
                }
            }
            if (offd) {
                #pragma unroll
                for (int off = 4; off <= 16; off <<= 1) {
                    u64 o;
                    o = __shfl_xor_sync(0xffffffffu, pk0, off); if (o > pk0) pk0 = o;
                    o = __shfl_xor_sync(0xffffffffu, pk1, off); if (o > pk1) pk1 = o;
                    o = __shfl_xor_sync(0xffffffffu, nk0, off); if (o < nk0) nk0 = o;
                    o = __shfl_xor_sync(0xffffffffu, nk1, off); if (o < nk1) nk1 = o;
                }
                if (rg == 0) {
                    atomicMax(&g_pkey[j0], pk0);
                    atomicMax(&g_pkey[j0 + 1], pk1);
                    atomicMin(&g_nkey[j0], nk0);
                    atomicMin(&g_nkey[j0 + 1], nk1);
                }
            }
        }

        CPA_WAIT0();
        __syncthreads();
    }

    // ---- flush row-side running state ----
    #pragma unroll
    for (int r = 0; r < 4; r++) {
        float pv = rpv[r]; int pi2 = rpi[r];
        float nv = rnv[r]; int ni2 = rni[r];
        #pragma unroll
        for (int off = 1; off <= 2; off <<= 1) {
            float ov = __shfl_xor_sync(0xffffffffu, pv, off);
            int oi = __shfl_xor_sync(0xffffffffu, pi2, off);
            if (ov > pv || (ov == pv && oi < pi2)) { pv = ov; pi2 = oi; }
            ov = __shfl_xor_sync(0xffffffffu, nv, off);
            oi = __shfl_xor_sync(0xffffffffu, ni2, off);
            if (ov < nv || (ov == nv && oi < ni2)) { nv = ov; ni2 = oi; }
        }
        if (tq == 0) {
            int row = ib + wm * 32 + (r >> 1) * 16 + (r & 1) * 8 + rg;
            atomicMax(&g_pkey[row], ((u64)encf(pv) << 32) | (uint32_t)(~(uint32_t)pi2));
            atomicMin(&g_nkey[row], ((u64)encf(nv) << 32) | (uint32_t)ni2);
        }
    }
}

// ---------------- K3: decode keys, gather triplets, partial sums ----------------
__global__ void terms_kernel(const float* __restrict__ x, const int* __restrict__ tg) {
    __shared__ float red[4 * 9];
    int tid = threadIdx.x;
    int lane = tid & 31, wrp = tid >> 5;
    int row = blockIdx.x * 128 + tid;

    u64 pk = g_pkey[row], nk = g_nkey[row];
    int gp = (int)(~(uint32_t)pk);
    int gn = (int)((uint32_t)nk);

    int t = tg[row];
    int cs = g_hist[t];
    float vf = (cs > 1 && (NN - cs) >= 1) ? 1.0f : 0.0f;
    gp = min(max(gp, 0), NN - 1);
    gn = min(max(gn, 0), NN - 1);
    int ppos = g_ps[t * NN + gp] - 1;
    int pneg = gn - g_ps[t * NN + gn];
    ppos = min(max(ppos, 0), NN - 1);
    pneg = min(max(pneg, 0), NN - 1);

    const float4* A = reinterpret_cast<const float4*>(x) + (size_t)row * 32;
    const float4* P = reinterpret_cast<const float4*>(x) + (size_t)ppos * 32;
    const float4* Q = reinterpret_cast<const float4*>(x) + (size_t)pneg * 32;
    float ap = 0, an = 0, npd = 0, l1a = 0, l1p = 0, l1n = 0;
    #pragma unroll
    for (int q = 0; q < 32; q++) {
        float4 a = A[q], p = P[q], n = Q[q];
        float d;
        d = a.x - p.x; ap = fmaf(d, d, ap);
        d = a.y - p.y; ap = fmaf(d, d, ap);
        d = a.z - p.z; ap = fmaf(d, d, ap);
        d = a.w - p.w; ap = fmaf(d, d, ap);
        d = a.x - n.x; an = fmaf(d, d, an);
        d = a.y - n.y; an = fmaf(d, d, an);
        d = a.z - n.z; an = fmaf(d, d, an);
        d = a.w - n.w; an = fmaf(d, d, an);
        d = p.x - n.x; npd = fmaf(d, d, npd);
        d = p.y - n.y; npd = fmaf(d, d, npd);
        d = p.z - n.z; npd = fmaf(d, d, npd);
        d = p.w - n.w; npd = fmaf(d, d, npd);
        l1a += fabsf(a.x) + fabsf(a.y) + fabsf(a.z) + fabsf(a.w);
        l1p += fabsf(p.x) + fabsf(p.y) + fabsf(p.z) + fabsf(p.w);
        l1n += fabsf(n.x) + fabsf(n.y) + fabsf(n.z) + fabsf(n.w);
    }
    float tl = fmaxf(ap - an + FMARGIN, 0.0f) * vf;

    float vals[9];
    vals[0] = tl;
    vals[1] = (tl > 0.0f) ? 1.0f : 0.0f;
    vals[2] = l1a * vf;
    vals[3] = l1p * vf;
    vals[4] = l1n * vf;
    vals[5] = ap * vf;
    vals[6] = an * vf;
    vals[7] = (ap - an - npd) * vf;
    vals[8] = vf;

    #pragma unroll
    for (int k = 0; k < 9; k++) {
        float v = vals[k];
        #pragma unroll
        for (int o = 16; o > 0; o >>= 1) v += __shfl_down_sync(0xffffffffu, v, o);
        if (lane == 0) red[wrp * 9 + k] = v;
    }
    __syncthreads();
    if (tid < 9)
        g_part[blockIdx.x * 9 + tid] = red[tid] + red[9 + tid] + red[18 + tid] + red[27 + tid];
}

// ---------------- K4: finalize ----------------
__global__ void final_kernel(float* __restrict__ out, int out_size) {
    __shared__ float r[6];
    if (threadIdx.x == 0) {
        float s[9];
        for (int k = 0; k < 9; k++) s[k] = 0.0f;
        for (int b = 0; b < 64; b++)
            for (int k = 0; k < 9; k++) s[k] += g_part[b * 9 + k];
        float vcount = s[8];
        float inv = (vcount > 0.0f) ? (1.0f / vcount) : 0.0f;
        float trip = (s[1] > 0.0f) ? (s[0] / s[1]) : (s[0] * inv);
        float sparse = (s[2] + s[3] + s[4]) * inv * (1.0f / 3.0f);
        float pw = s[7] * inv;
        if (pw < 0.0f) pw = 0.0f;
        r[0] = trip; r[1] = sparse; r[2] = pw;
        r[3] = vcount; r[4] = s[5] * inv; r[5] = s[6] * inv;
    }
    __syncthreads();
    for (int i = threadIdx.x; i < out_size; i += blockDim.x)
        out[i] = (i < 6) ? r[i] : 0.0f;
}

// ---------------- launch ----------------
extern "C" void kernel_launch(void* const* d_in, const int* in_sizes, int n_in,
                              void* d_out, int out_size) {
    const float* x = (const float*)d_in[0];
    const int* tg = (const int*)d_in[1];

    cudaFuncSetAttribute(dist_mma_kernel, cudaFuncAttributeMaxDynamicSharedMemorySize,
                         S_TOT);

    init_keys<<<NN / 256, 256>>>();
    prep_kernel<<<64, 128>>>(x);
    prefix_kernel<<<CC, 256>>>(tg);
    dist_mma_kernel<<<NCTAS, NTHREADS, S_TOT>>>(tg);
    terms_kernel<<<64, 128>>>(x, tg);
    final_kernel<<<1, 64>>>((float*)d_out, out_size);
}